// round 11
// baseline (speedup 1.0000x reference)
#include <cuda_runtime.h>
#include <cuda_fp16.h>
#include <math.h>
#include <cstdint>

#define S 256
#define B 64
#define D 512
#define T 64
#define V 32000
#define GD 2048  /* 4*D */
#define NCTA 128 /* persistent loop grid */

// ---------------- scratch (device globals; no runtime allocation) ----------
__device__ float g_xw[(size_t)T * B * GD];        // x@W_ih^T + b_ih + b_hh
__device__ float g_cbuf[2 * B * D];               // double-buffered cell state
__device__ float g_gpart[4 * B * GD];             // k-split partial gate sums
__device__ float g_scraw[B * S];                  // raw per-step scores
__device__ float g_hcall[(size_t)T * B * D];      // hc pre-LN
__device__ __half g_peh[(size_t)T * B * D];
__device__ __half g_pel[(size_t)T * B * D];
__device__ __half g_embh[(size_t)V * D];
__device__ __half g_embl[(size_t)V * D];
__device__ __half g_whh_h[(size_t)GD * D];
__device__ __half g_whh_l[(size_t)GD * D];
__device__ __half g_wih_h[(size_t)GD * D];
__device__ __half g_wih_l[(size_t)GD * D];
__device__ __half g_whc_h[(size_t)D * 2 * D];
__device__ __half g_whc_l[(size_t)D * 2 * D];
__device__ __half g_hh16[B * D];                  // current h, fp16 hi
__device__ __half g_hl16[B * D];                  // current h, fp16 lo
__device__ __half g_hcinh[(size_t)T * B * 2 * D]; // [h|ctx] hi, [4096,1024]
__device__ __half g_hcinl[(size_t)T * B * 2 * D]; // [h|ctx] lo
__device__ unsigned g_bar_cnt;
__device__ unsigned g_bar_gen;

__device__ __forceinline__ float sigf(float x) { return 1.f / (1.f + expf(-x)); }

// ======================= PTX helpers ========================================
__device__ __forceinline__ uint32_t smem_u32(const void* p) {
    uint32_t a;
    asm("{ .reg .u64 t; cvta.to.shared.u64 t, %1; cvt.u32.u64 %0, t; }" : "=r"(a) : "l"(p));
    return a;
}
__device__ __forceinline__ uint32_t sw128(uint32_t off) { return off ^ ((off >> 3) & 0x70); }

#define CP_ASYNC16(dst, src) \
    asm volatile("cp.async.cg.shared.global [%0], [%1], 16;" :: "r"(dst), "l"(src) : "memory")
#define CP_COMMIT() asm volatile("cp.async.commit_group;" ::: "memory")
#define CP_WAIT(n) asm volatile("cp.async.wait_group %0;" :: "n"(n) : "memory")

__device__ __forceinline__ void ldsm_x4(uint32_t* r, uint32_t addr) {
    asm volatile("ldmatrix.sync.aligned.m8n8.x4.shared.b16 {%0,%1,%2,%3}, [%4];"
                 : "=r"(r[0]), "=r"(r[1]), "=r"(r[2]), "=r"(r[3]) : "r"(addr));
}
__device__ __forceinline__ void mma16816(float* c, const uint32_t* a, uint32_t b0, uint32_t b1) {
    asm volatile(
        "mma.sync.aligned.m16n8k16.row.col.f32.f16.f16.f32 "
        "{%0,%1,%2,%3}, {%4,%5,%6,%7}, {%8,%9}, {%0,%1,%2,%3};"
        : "+f"(c[0]), "+f"(c[1]), "+f"(c[2]), "+f"(c[3])
        : "r"(a[0]), "r"(a[1]), "r"(a[2]), "r"(a[3]), "r"(b0), "r"(b1));
}

// software grid barrier — all NCTA CTAs co-resident by construction
__device__ __forceinline__ void grid_bar() {
    __syncthreads();
    if (threadIdx.x == 0) {
        __threadfence();
        unsigned gen = *(volatile unsigned*)&g_bar_gen;
        if (atomicAdd(&g_bar_cnt, 1u) == NCTA - 1) {
            g_bar_cnt = 0;
            __threadfence();
            *(volatile unsigned*)&g_bar_gen = gen + 1;
        } else {
            while (*(volatile unsigned*)&g_bar_gen == gen) { }
        }
        __threadfence();
    }
    __syncthreads();
}

// ---------------- init h0 = c0 = feats[S-1] --------------------------------
__global__ void k_init(const float* __restrict__ feats) {
    int i = blockIdx.x * blockDim.x + threadIdx.x;
    float v = feats[(size_t)(S - 1) * B * D + i];
    g_cbuf[i] = v;                      // buffer 0
    __half hh = __float2half_rn(v);
    g_hh16[i] = hh;
    g_hl16[i] = __float2half_rn(v - __half2float(hh));
}

// ---------------- fp32 -> fp16 hi/lo converter ------------------------------
__global__ void k_cvt(const float* __restrict__ src, __half* __restrict__ dh,
                      __half* __restrict__ dl) {
    int i = blockIdx.x * blockDim.x + threadIdx.x;
    float4 x = ((const float4*)src)[i];
    __half h0 = __float2half_rn(x.x), h1 = __float2half_rn(x.y);
    __half h2 = __float2half_rn(x.z), h3 = __float2half_rn(x.w);
    __half2 ph0 = {h0, h1}, ph1 = {h2, h3};
    __half2 pl0 = {__float2half_rn(x.x - __half2float(h0)),
                   __float2half_rn(x.y - __half2float(h1))};
    __half2 pl1 = {__float2half_rn(x.z - __half2float(h2)),
                   __float2half_rn(x.w - __half2float(h3))};
    ((__half2*)dh)[2 * i] = ph0;
    ((__half2*)dh)[2 * i + 1] = ph1;
    ((__half2*)dl)[2 * i] = pl0;
    ((__half2*)dl)[2 * i + 1] = pl1;
}

// ======================= shared mma tile machinery ==========================
#define LG_KC 64
#define LG_COMP_BYTES (128 * 128)
#define LG_STAGE_BYTES (4 * LG_COMP_BYTES)
#define LG_SMEM_REQ (2 * LG_STAGE_BYTES + 1024)

template <int KCH, typename ISSUE>
__device__ __forceinline__ void mma_tile_128(uint32_t sb, ISSUE issue,
                                             float (&acc)[2][8][4],
                                             int warp, int lane) {
    int wm = warp & 3, wn = warp >> 2;
    issue(0, 0);
    for (int c = 0; c < KCH; c++) {
        if (c + 1 < KCH) {
            issue(c + 1, (c + 1) & 1);
            CP_WAIT(1);
        } else {
            CP_WAIT(0);
        }
        __syncthreads();
        uint32_t st = sb + (c & 1) * LG_STAGE_BYTES;
        uint32_t Ah_b = st, Al_b = st + LG_COMP_BYTES;
        uint32_t Bh_b = st + 2 * LG_COMP_BYTES, Bl_b = st + 3 * LG_COMP_BYTES;
        int lrow = lane & 15;
        uint32_t lcol = (uint32_t)((lane >> 4) << 4);
#pragma unroll
        for (int ks = 0; ks < 4; ks++) {
            uint32_t ah[2][4], al[2][4];
#pragma unroll
            for (int mt = 0; mt < 2; mt++) {
                int r = wm * 32 + mt * 16 + lrow;
                uint32_t bo = sw128((uint32_t)(r * 128 + ks * 32) + lcol);
                ldsm_x4(ah[mt], Ah_b + bo);
                ldsm_x4(al[mt], Al_b + bo);
            }
            uint32_t bh[4][4], bl[4][4];
#pragma unroll
            for (int p = 0; p < 4; p++) {
                int r = wn * 64 + p * 16 + lrow;
                uint32_t bo = sw128((uint32_t)(r * 128 + ks * 32) + lcol);
                ldsm_x4(bh[p], Bh_b + bo);
                ldsm_x4(bl[p], Bl_b + bo);
            }
#pragma unroll
            for (int mt = 0; mt < 2; mt++)
#pragma unroll
                for (int p = 0; p < 4; p++) {
#pragma unroll
                    for (int q = 0; q < 2; q++) {
                        int nt = p * 2 + q;
                        mma16816(acc[mt][nt], ah[mt], bh[p][q], bh[p][q + 2]);
                        mma16816(acc[mt][nt], ah[mt], bl[p][q], bl[p][q + 2]);
                        mma16816(acc[mt][nt], al[mt], bh[p][q], bh[p][q + 2]);
                    }
                }
        }
        __syncthreads();
    }
}

// ---------------- xW = emb[labels] @ W_ih^T + b_ih + b_hh (mma) ------------
__global__ __launch_bounds__(256) void k_xw_mma(const int* __restrict__ labels,
                                                const float* __restrict__ b_ih,
                                                const float* __restrict__ b_hh) {
    extern __shared__ char smraw[];
    __shared__ int rowlab[128];
    uint32_t sb = (smem_u32(smraw) + 1023u) & ~1023u;
    int tid = threadIdx.x, warp = tid >> 5, lane = tid & 31;
    int n0 = blockIdx.x * 128, m0 = blockIdx.y * 128;
    if (tid < 128) {
        int m = m0 + tid;
        int lab = labels[(m & 63) * T + (m >> 6)];
        rowlab[tid] = lab < 0 ? 0 : (lab >= V ? V - 1 : lab);
    }
    __syncthreads();
    auto issue = [&](int c, int stage) {
        uint32_t sbase = sb + stage * LG_STAGE_BYTES;
#pragma unroll
        for (int i = 0; i < 16; i++) {
            int slot = i * 256 + tid;
            int comp = slot >> 10, w = slot & 1023;
            int r = w >> 3, ch = w & 7;
            const __half* src;
            if (comp == 0)      src = g_embh + (size_t)rowlab[r] * D;
            else if (comp == 1) src = g_embl + (size_t)rowlab[r] * D;
            else if (comp == 2) src = g_wih_h + (size_t)(n0 + r) * D;
            else                src = g_wih_l + (size_t)(n0 + r) * D;
            src += c * LG_KC + ch * 8;
            uint32_t dst = sbase + comp * LG_COMP_BYTES + sw128(r * 128 + ch * 16);
            CP_ASYNC16(dst, src);
        }
        CP_COMMIT();
    };
    float acc[2][8][4] = {};
    mma_tile_128<D / LG_KC>(sb, issue, acc, warp, lane);
    int wm = warp & 3, wn = warp >> 2;
#pragma unroll
    for (int mt = 0; mt < 2; mt++) {
        int mrow = m0 + wm * 32 + mt * 16 + (lane >> 2);
#pragma unroll
        for (int nt = 0; nt < 8; nt++) {
            int n = n0 + wn * 64 + nt * 8 + (lane & 3) * 2;
            float2 bi = *(const float2*)(b_ih + n);
            float2 bh2 = *(const float2*)(b_hh + n);
            float2 o0 = {acc[mt][nt][0] + bi.x + bh2.x, acc[mt][nt][1] + bi.y + bh2.y};
            float2 o1 = {acc[mt][nt][2] + bi.x + bh2.x, acc[mt][nt][3] + bi.y + bh2.y};
            *(float2*)(g_xw + (size_t)mrow * GD + n) = o0;
            *(float2*)(g_xw + (size_t)(mrow + 8) * GD + n) = o1;
        }
    }
}

// ============ persistent recurrence: gates mma + cell + attention ===========
// grid NCTA=128 x 256 thr. Per step:
//   G : CTA (n-tile = cta&31, ksplit = cta>>5) computes 64x64 gate tile, K=128
//   B1
//   C1: CTA pair (b = cta>>1, half = cta&1): cell (redundant), scores s-half
//   B2
//   C2: softmax (redundant per pair) + ctx d-half    [overlaps next G via slack]
#define GT_COMP_BYTES (64 * 128)
__global__ __launch_bounds__(256) void k_loop(const float* __restrict__ feats) {
    __shared__ __align__(1024) char sm[4 * GT_COMP_BYTES];
    float* hs = (float*)sm;                       // 512 floats (C1)
    float* wsc = (float*)(sm + 2048);             // 256 floats (C2)
    float* red = (float*)(sm + 3072);             // 256 floats (C1/C2 reductions)
    uint32_t sb = smem_u32(sm);
    int tid = threadIdx.x, warp = tid >> 5, lane = tid & 31;
    int cta = blockIdx.x;
    int n0 = (cta & 31) * 64;                     // gate-dim tile
    int ksplit = cta >> 5;                        // 0..3
    int b = cta >> 1, half = cta & 1;
    int wm = warp & 1, wn = warp >> 1;
    int lrow = lane & 15;
    uint32_t lcol = (uint32_t)((lane >> 4) << 4);

    for (int t = 0; t < T; t++) {
        // ---------------- Phase G: gates partial mma ----------------
        {
            float acc[2][2][4] = {};
#pragma unroll
            for (int sub = 0; sub < 2; sub++) {
                int kb = ksplit * 128 + sub * 64;
                const __half* srcs[4] = {g_hh16, g_hl16,
                                         g_whh_h + (size_t)n0 * D,
                                         g_whh_l + (size_t)n0 * D};
#pragma unroll
                for (int i = 0; i < 8; i++) {
                    int slot = i * 256 + tid;
                    int comp = slot >> 9, w = slot & 511;
                    int r = w >> 3, ch = w & 7;
                    const __half* src = srcs[comp] + (size_t)r * D + kb + ch * 8;
                    uint32_t dst = sb + comp * GT_COMP_BYTES + sw128(r * 128 + ch * 16);
                    CP_ASYNC16(dst, src);
                }
                CP_COMMIT();
                CP_WAIT(0);
                __syncthreads();
                uint32_t Ah_b = sb, Al_b = sb + GT_COMP_BYTES;
                uint32_t Bh_b = sb + 2 * GT_COMP_BYTES, Bl_b = sb + 3 * GT_COMP_BYTES;
#pragma unroll
                for (int ks = 0; ks < 4; ks++) {
                    uint32_t ah[2][4], al[2][4];
#pragma unroll
                    for (int mt = 0; mt < 2; mt++) {
                        int r = wm * 32 + mt * 16 + lrow;
                        uint32_t bo = sw128((uint32_t)(r * 128 + ks * 32) + lcol);
                        ldsm_x4(ah[mt], Ah_b + bo);
                        ldsm_x4(al[mt], Al_b + bo);
                    }
                    uint32_t bh[4], bl[4];
                    {
                        int r = wn * 16 + lrow;
                        uint32_t bo = sw128((uint32_t)(r * 128 + ks * 32) + lcol);
                        ldsm_x4(bh, Bh_b + bo);
                        ldsm_x4(bl, Bl_b + bo);
                    }
#pragma unroll
                    for (int mt = 0; mt < 2; mt++)
#pragma unroll
                        for (int q = 0; q < 2; q++) {
                            mma16816(acc[mt][q], ah[mt], bh[q], bh[q + 2]);
                            mma16816(acc[mt][q], ah[mt], bl[q], bl[q + 2]);
                            mma16816(acc[mt][q], al[mt], bh[q], bh[q + 2]);
                        }
                }
                __syncthreads();
            }
            float* base = g_gpart + (size_t)ksplit * B * GD;
#pragma unroll
            for (int mt = 0; mt < 2; mt++) {
                int br = wm * 32 + mt * 16 + (lane >> 2);
#pragma unroll
                for (int q = 0; q < 2; q++) {
                    int n = n0 + wn * 16 + q * 8 + (lane & 3) * 2;
                    float2 o0 = {acc[mt][q][0], acc[mt][q][1]};
                    float2 o1 = {acc[mt][q][2], acc[mt][q][3]};
                    *(float2*)(base + (size_t)br * GD + n) = o0;
                    *(float2*)(base + (size_t)(br + 8) * GD + n) = o1;
                }
            }
        }
        grid_bar();   // B1: gparts ready; G's hh16 reads done

        // ---------------- Phase C1: cell + scores ----------------
        {
            const float* c_in = g_cbuf + (t & 1) * (B * D);
            float* c_out = g_cbuf + ((t + 1) & 1) * (B * D);
            const float* xwrow = g_xw + ((size_t)t * B + b) * GD;
#pragma unroll
            for (int dd = 0; dd < 2; dd++) {
                int d = tid + dd * 256;
                float ig = xwrow[d], fg = xwrow[D + d];
                float gg = xwrow[2 * D + d], og = xwrow[3 * D + d];
#pragma unroll
                for (int ks = 0; ks < 4; ks++) {
                    const float* gp = g_gpart + ((size_t)ks * B + b) * GD;
                    ig += gp[d];
                    fg += gp[D + d];
                    gg += gp[2 * D + d];
                    og += gp[3 * D + d];
                }
                float cn = sigf(fg) * c_in[b * D + d] + sigf(ig) * tanhf(gg);
                float hv = sigf(og) * tanhf(cn);
                hs[d] = hv;
                if (half == 0) {
                    c_out[b * D + d] = cn;
                    __half hhv = __float2half_rn(hv);
                    __half hlv = __float2half_rn(hv - __half2float(hhv));
                    g_hh16[b * D + d] = hhv;
                    g_hl16[b * D + d] = hlv;
                    size_t mrow = (size_t)t * B + b;
                    g_hcinh[mrow * 2 * D + d] = hhv;
                    g_hcinl[mrow * 2 * D + d] = hlv;
                }
            }
            __syncthreads();
            const float4* h4 = (const float4*)hs;
#pragma unroll
            for (int i = 0; i < 16; i++) {
                int s = half * 128 + warp * 16 + i;
                const float4* f4 = (const float4*)(feats + ((size_t)s * B + b) * D);
                float a = 0.f;
#pragma unroll
                for (int j = 0; j < 4; j++) {
                    int ii = j * 32 + lane;
                    float4 f = f4[ii], h = h4[ii];
                    a = fmaf(f.x, h.x, fmaf(f.y, h.y, fmaf(f.z, h.z, fmaf(f.w, h.w, a))));
                }
#pragma unroll
                for (int o = 16; o; o >>= 1) a += __shfl_xor_sync(0xffffffffu, a, o);
                if (lane == 0) g_scraw[b * S + s] = a;
            }
        }
        grid_bar();   // B2: all scores + h(fp16) + c_out visible

        // ---------------- Phase C2: softmax + ctx ----------------
        {
            float sv = g_scraw[b * S + tid];
            red[tid] = sv;
            __syncthreads();
            for (int st = 128; st; st >>= 1) {
                if (tid < st) red[tid] = fmaxf(red[tid], red[tid + st]);
                __syncthreads();
            }
            float mx = red[0];
            __syncthreads();
            float e = expf(sv - mx);
            red[tid] = e;
            __syncthreads();
            for (int st = 128; st; st >>= 1) {
                if (tid < st) red[tid] += red[tid + st];
                __syncthreads();
            }
            wsc[tid] = e / red[0];
            __syncthreads();
            int d = half * 256 + tid;
            const float* fp = feats + (size_t)b * D + d;
            float a = 0.f;
#pragma unroll 8
            for (int s2 = 0; s2 < S; s2++)
                a = fmaf(wsc[s2], fp[(size_t)s2 * B * D], a);
            __half ch = __float2half_rn(a);
            size_t mrow = (size_t)t * B + b;
            g_hcinh[mrow * 2 * D + D + d] = ch;
            g_hcinl[mrow * 2 * D + D + d] = __float2half_rn(a - __half2float(ch));
            __syncthreads();   // protect wsc/red before next-step smem reuse
        }
        // no grid barrier needed: next G touches hh16/whh/gpart only;
        // scraw reuse is fenced by next step's B1.
    }
}

// ---------------- hcall = [h, ctx] @ W_hc^T + b_hc (mma) --------------------
__global__ __launch_bounds__(256) void k_hc_mma(const float* __restrict__ b_hc) {
    extern __shared__ char smraw[];
    uint32_t sb = (smem_u32(smraw) + 1023u) & ~1023u;
    int tid = threadIdx.x, warp = tid >> 5, lane = tid & 31;
    int n0 = blockIdx.x * 128, m0 = blockIdx.y * 128;
    auto issue = [&](int c, int stage) {
        uint32_t sbase = sb + stage * LG_STAGE_BYTES;
#pragma unroll
        for (int i = 0; i < 16; i++) {
            int slot = i * 256 + tid;
            int comp = slot >> 10, w = slot & 1023;
            int r = w >> 3, ch = w & 7;
            const __half* src;
            if (comp == 0)      src = g_hcinh + (size_t)(m0 + r) * 2 * D;
            else if (comp == 1) src = g_hcinl + (size_t)(m0 + r) * 2 * D;
            else if (comp == 2) src = g_whc_h + (size_t)(n0 + r) * 2 * D;
            else                src = g_whc_l + (size_t)(n0 + r) * 2 * D;
            src += c * LG_KC + ch * 8;
            uint32_t dst = sbase + comp * LG_COMP_BYTES + sw128(r * 128 + ch * 16);
            CP_ASYNC16(dst, src);
        }
        CP_COMMIT();
    };
    float acc[2][8][4] = {};
    mma_tile_128<2 * D / LG_KC>(sb, issue, acc, warp, lane);
    int wm = warp & 3, wn = warp >> 2;
#pragma unroll
    for (int mt = 0; mt < 2; mt++) {
        int mrow = m0 + wm * 32 + mt * 16 + (lane >> 2);
#pragma unroll
        for (int nt = 0; nt < 8; nt++) {
            int n = n0 + wn * 64 + nt * 8 + (lane & 3) * 2;
            float2 bv = *(const float2*)(b_hc + n);
            float2 o0 = {acc[mt][nt][0] + bv.x, acc[mt][nt][1] + bv.y};
            float2 o1 = {acc[mt][nt][2] + bv.x, acc[mt][nt][3] + bv.y};
            *(float2*)(g_hcall + (size_t)mrow * D + n) = o0;
            *(float2*)(g_hcall + (size_t)(mrow + 8) * D + n) = o1;
        }
    }
}

// ---------------- LayerNorm + tanh -> pe (fp16 hi/lo, fused) ---------------
__global__ __launch_bounds__(128) void k_ln_all(const float* __restrict__ ln_g,
                                                const float* __restrict__ ln_b) {
    int m = blockIdx.x;
    int tid = threadIdx.x;
    __shared__ float wsum[4];
    float4 x = *(const float4*)(g_hcall + (size_t)m * D + tid * 4);
    float s = x.x + x.y + x.z + x.w;
#pragma unroll
    for (int o = 16; o; o >>= 1) s += __shfl_xor_sync(0xffffffff, s, o);
    if ((tid & 31) == 0) wsum[tid >> 5] = s;
    __syncthreads();
    float mean = (wsum[0] + wsum[1] + wsum[2] + wsum[3]) * (1.f / D);
    float4 dv = {x.x - mean, x.y - mean, x.z - mean, x.w - mean};
    float v = dv.x * dv.x + dv.y * dv.y + dv.z * dv.z + dv.w * dv.w;
#pragma unroll
    for (int o = 16; o; o >>= 1) v += __shfl_xor_sync(0xffffffff, v, o);
    __syncthreads();
    if ((tid & 31) == 0) wsum[tid >> 5] = v;
    __syncthreads();
    float var = (wsum[0] + wsum[1] + wsum[2] + wsum[3]) * (1.f / D);
    float rs = rsqrtf(var + 1e-5f);
    float4 gl = *(const float4*)(ln_g + tid * 4);
    float4 bl = *(const float4*)(ln_b + tid * 4);
    float y0 = tanhf(fmaf(gl.x, dv.x * rs, bl.x));
    float y1 = tanhf(fmaf(gl.y, dv.y * rs, bl.y));
    float y2 = tanhf(fmaf(gl.z, dv.z * rs, bl.z));
    float y3 = tanhf(fmaf(gl.w, dv.w * rs, bl.w));
    __half h0 = __float2half_rn(y0), h1 = __float2half_rn(y1);
    __half h2 = __float2half_rn(y2), h3 = __float2half_rn(y3);
    size_t o = (size_t)m * D + tid * 4;
    *(__half2*)&g_peh[o] = {h0, h1};
    *(__half2*)&g_peh[o + 2] = {h2, h3};
    *(__half2*)&g_pel[o] = {__float2half_rn(y0 - __half2float(h0)),
                            __float2half_rn(y1 - __half2float(h1))};
    *(__half2*)&g_pel[o + 2] = {__float2half_rn(y2 - __half2float(h2)),
                                __float2half_rn(y3 - __half2float(h3))};
}

// ============ logits via mma.sync fp16 hi/lo split ==========================
__global__ __launch_bounds__(256) void k_logits_mma(const float* __restrict__ vbias,
                                                    float* __restrict__ out) {
    extern __shared__ char smraw[];
    uint32_t sb = (smem_u32(smraw) + 1023u) & ~1023u;
    int tid = threadIdx.x, warp = tid >> 5, lane = tid & 31;
    int m0 = blockIdx.x * 128, n0 = blockIdx.y * 128;
    const __half* srcs[4] = {g_peh + (size_t)m0 * D, g_pel + (size_t)m0 * D,
                             g_embh + (size_t)n0 * D, g_embl + (size_t)n0 * D};
    auto issue = [&](int c, int stage) {
        uint32_t sbase = sb + stage * LG_STAGE_BYTES;
#pragma unroll
        for (int i = 0; i < 16; i++) {
            int slot = i * 256 + tid;
            int comp = slot >> 10, w = slot & 1023;
            int r = w >> 3, ch = w & 7;
            const __half* src = srcs[comp] + (size_t)r * D + c * LG_KC + ch * 8;
            uint32_t dst = sbase + comp * LG_COMP_BYTES + sw128(r * 128 + ch * 16);
            CP_ASYNC16(dst, src);
        }
        CP_COMMIT();
    };
    float acc[2][8][4] = {};
    mma_tile_128<D / LG_KC>(sb, issue, acc, warp, lane);
    int wm = warp & 3, wn = warp >> 2;
#pragma unroll
    for (int mt = 0; mt < 2; mt++) {
        int mrow = m0 + wm * 32 + mt * 16 + (lane >> 2);
#pragma unroll
        for (int nt = 0; nt < 8; nt++) {
            int n = n0 + wn * 64 + nt * 8 + (lane & 3) * 2;
            float2 bv = *(const float2*)(vbias + n);
            float2 o0 = {acc[mt][nt][0] + bv.x, acc[mt][nt][1] + bv.y};
            float2 o1 = {acc[mt][nt][2] + bv.x, acc[mt][nt][3] + bv.y};
            *(float2*)(out + (size_t)mrow * V + n) = o0;
            *(float2*)(out + (size_t)(mrow + 8) * V + n) = o1;
        }
    }
}

// ---------------- launch ----------------------------------------------------
extern "C" void kernel_launch(void* const* d_in, const int* in_sizes, int n_in,
                              void* d_out, int out_size) {
    const float* feats = (const float*)d_in[0];
    const int* labels = (const int*)d_in[1];
    const float* W_ih = (const float*)d_in[2];
    const float* W_hh = (const float*)d_in[3];
    const float* b_ih = (const float*)d_in[4];
    const float* b_hh = (const float*)d_in[5];
    const float* W_hc = (const float*)d_in[6];
    const float* b_hc = (const float*)d_in[7];
    const float* ln_g = (const float*)d_in[8];
    const float* ln_b = (const float*)d_in[9];
    const float* emb = (const float*)d_in[10];
    const float* vbias = (const float*)d_in[11];
    float* out = (float*)d_out;

    cudaFuncSetAttribute(k_logits_mma, cudaFuncAttributeMaxDynamicSharedMemorySize,
                         LG_SMEM_REQ);
    cudaFuncSetAttribute(k_xw_mma, cudaFuncAttributeMaxDynamicSharedMemorySize,
                         LG_SMEM_REQ);
    cudaFuncSetAttribute(k_hc_mma, cudaFuncAttributeMaxDynamicSharedMemorySize,
                         LG_SMEM_REQ);

    __half *embh, *embl, *whhh, *whhl, *wihh, *wihl, *whch, *whcl;
    cudaGetSymbolAddress((void**)&embh, g_embh);
    cudaGetSymbolAddress((void**)&embl, g_embl);
    cudaGetSymbolAddress((void**)&whhh, g_whh_h);
    cudaGetSymbolAddress((void**)&whhl, g_whh_l);
    cudaGetSymbolAddress((void**)&wihh, g_wih_h);
    cudaGetSymbolAddress((void**)&wihl, g_wih_l);
    cudaGetSymbolAddress((void**)&whch, g_whc_h);
    cudaGetSymbolAddress((void**)&whcl, g_whc_l);

    k_init<<<(B * D) / 256, 256>>>(feats);
    k_cvt<<<(V * D / 4) / 256, 256>>>(emb, embh, embl);
    k_cvt<<<(GD * D / 4) / 256, 256>>>(W_hh, whhh, whhl);
    k_cvt<<<(GD * D / 4) / 256, 256>>>(W_ih, wihh, wihl);
    k_cvt<<<(D * 2 * D / 4) / 256, 256>>>(W_hc, whch, whcl);
    k_xw_mma<<<dim3(GD / 128, (T * B) / 128), 256, LG_SMEM_REQ>>>(labels, b_ih, b_hh);
    k_loop<<<NCTA, 256>>>(feats);
    k_hc_mma<<<dim3(D / 128, (T * B) / 128), 256, LG_SMEM_REQ>>>(b_hc);
    k_ln_all<<<T * B, 128>>>(ln_g, ln_b);
    k_logits_mma<<<dim3((T * B) / 128, V / 128), 256, LG_SMEM_REQ>>>(vbias, out);
}

// round 12
// speedup vs baseline: 1.1306x; 1.1306x over previous
#include <cuda_runtime.h>
#include <cuda_fp16.h>
#include <math.h>
#include <cstdint>

#define S 256
#define B 64
#define D 512
#define T 64
#define V 32000
#define GD 2048  /* 4*D */

// ---------------- scratch (device globals; no runtime allocation) ----------
__device__ float g_xw[(size_t)T * B * GD];        // x@W_ih^T + b_ih + b_hh
__device__ float g_cbuf[2 * B * D];               // double-buffered cell state
__device__ float g_gpart[8 * B * GD];             // k-split partial gate sums
__device__ float g_hcall[(size_t)T * B * D];      // hc pre-LN
__device__ __half g_feats16[(size_t)S * B * D];   // feats in fp16 (ctx only)
__device__ __half g_peh[(size_t)T * B * D];
__device__ __half g_pel[(size_t)T * B * D];
__device__ __half g_embh[(size_t)V * D];
__device__ __half g_embl[(size_t)V * D];
__device__ __half g_whh_h[(size_t)GD * D];
__device__ __half g_whh_l[(size_t)GD * D];
__device__ __half g_wih_h[(size_t)GD * D];
__device__ __half g_wih_l[(size_t)GD * D];
__device__ __half g_whc_h[(size_t)D * 2 * D];
__device__ __half g_whc_l[(size_t)D * 2 * D];
__device__ __half g_hh16[B * D];                  // current h, fp16 hi
__device__ __half g_hl16[B * D];                  // current h, fp16 lo
__device__ __half g_hcinh[(size_t)T * B * 2 * D]; // [h|ctx] hi, [4096,1024]
__device__ __half g_hcinl[(size_t)T * B * 2 * D]; // [h|ctx] lo

__device__ __forceinline__ float sigf(float x) { return 1.f / (1.f + expf(-x)); }

// ======================= PTX helpers ========================================
__device__ __forceinline__ uint32_t smem_u32(const void* p) {
    uint32_t a;
    asm("{ .reg .u64 t; cvta.to.shared.u64 t, %1; cvt.u32.u64 %0, t; }" : "=r"(a) : "l"(p));
    return a;
}
__device__ __forceinline__ uint32_t sw128(uint32_t off) { return off ^ ((off >> 3) & 0x70); }

#define CP_ASYNC16(dst, src) \
    asm volatile("cp.async.cg.shared.global [%0], [%1], 16;" :: "r"(dst), "l"(src) : "memory")
#define CP_COMMIT() asm volatile("cp.async.commit_group;" ::: "memory")
#define CP_WAIT(n) asm volatile("cp.async.wait_group %0;" :: "n"(n) : "memory")

__device__ __forceinline__ void ldsm_x4(uint32_t* r, uint32_t addr) {
    asm volatile("ldmatrix.sync.aligned.m8n8.x4.shared.b16 {%0,%1,%2,%3}, [%4];"
                 : "=r"(r[0]), "=r"(r[1]), "=r"(r[2]), "=r"(r[3]) : "r"(addr));
}
__device__ __forceinline__ void mma16816(float* c, const uint32_t* a, uint32_t b0, uint32_t b1) {
    asm volatile(
        "mma.sync.aligned.m16n8k16.row.col.f32.f16.f16.f32 "
        "{%0,%1,%2,%3}, {%4,%5,%6,%7}, {%8,%9}, {%0,%1,%2,%3};"
        : "+f"(c[0]), "+f"(c[1]), "+f"(c[2]), "+f"(c[3])
        : "r"(a[0]), "r"(a[1]), "r"(a[2]), "r"(a[3]), "r"(b0), "r"(b1));
}

// DSMEM: store fp32 into peer CTA's smem at same offset
__device__ __forceinline__ void dsmem_st_f32(uint32_t local_addr, int peer_rank, float v) {
    uint32_t remote;
    asm volatile("mapa.shared::cluster.u32 %0, %1, %2;"
                 : "=r"(remote) : "r"(local_addr), "r"(peer_rank));
    asm volatile("st.shared::cluster.f32 [%0], %1;" :: "r"(remote), "f"(v) : "memory");
}
#define CLUSTER_SYNC() do { \
    asm volatile("barrier.cluster.arrive.aligned;" ::: "memory"); \
    asm volatile("barrier.cluster.wait.aligned;" ::: "memory"); \
} while (0)

// ---------------- init h0 = c0 = feats[S-1] --------------------------------
__global__ void k_init(const float* __restrict__ feats) {
    int i = blockIdx.x * blockDim.x + threadIdx.x;
    float v = feats[(size_t)(S - 1) * B * D + i];
    g_cbuf[i] = v;                      // buffer 0
    __half hh = __float2half_rn(v);
    g_hh16[i] = hh;
    g_hl16[i] = __float2half_rn(v - __half2float(hh));
}

// ---------------- fp32 -> fp16 hi/lo converter ------------------------------
__global__ void k_cvt(const float* __restrict__ src, __half* __restrict__ dh,
                      __half* __restrict__ dl) {
    int i = blockIdx.x * blockDim.x + threadIdx.x;
    float4 x = ((const float4*)src)[i];
    __half h0 = __float2half_rn(x.x), h1 = __float2half_rn(x.y);
    __half h2 = __float2half_rn(x.z), h3 = __float2half_rn(x.w);
    __half2 ph0 = {h0, h1}, ph1 = {h2, h3};
    __half2 pl0 = {__float2half_rn(x.x - __half2float(h0)),
                   __float2half_rn(x.y - __half2float(h1))};
    __half2 pl1 = {__float2half_rn(x.z - __half2float(h2)),
                   __float2half_rn(x.w - __half2float(h3))};
    ((__half2*)dh)[2 * i] = ph0;
    ((__half2*)dh)[2 * i + 1] = ph1;
    ((__half2*)dl)[2 * i] = pl0;
    ((__half2*)dl)[2 * i + 1] = pl1;
}

// ---------------- fp32 -> fp16 (single) converter ---------------------------
__global__ void k_cvt1(const float* __restrict__ src, __half* __restrict__ dh) {
    int i = blockIdx.x * blockDim.x + threadIdx.x;
    float4 x = ((const float4*)src)[i];
    __half2 p0 = {__float2half_rn(x.x), __float2half_rn(x.y)};
    __half2 p1 = {__float2half_rn(x.z), __float2half_rn(x.w)};
    ((__half2*)dh)[2 * i] = p0;
    ((__half2*)dh)[2 * i + 1] = p1;
}

// ======================= shared mma tile machinery ==========================
#define LG_KC 64
#define LG_COMP_BYTES (128 * 128)
#define LG_STAGE_BYTES (4 * LG_COMP_BYTES)
#define LG_SMEM_REQ (2 * LG_STAGE_BYTES + 1024)

template <int KCH, typename ISSUE>
__device__ __forceinline__ void mma_tile_128(uint32_t sb, ISSUE issue,
                                             float (&acc)[2][8][4],
                                             int warp, int lane) {
    int wm = warp & 3, wn = warp >> 2;
    issue(0, 0);
    for (int c = 0; c < KCH; c++) {
        if (c + 1 < KCH) {
            issue(c + 1, (c + 1) & 1);
            CP_WAIT(1);
        } else {
            CP_WAIT(0);
        }
        __syncthreads();
        uint32_t st = sb + (c & 1) * LG_STAGE_BYTES;
        uint32_t Ah_b = st, Al_b = st + LG_COMP_BYTES;
        uint32_t Bh_b = st + 2 * LG_COMP_BYTES, Bl_b = st + 3 * LG_COMP_BYTES;
        int lrow = lane & 15;
        uint32_t lcol = (uint32_t)((lane >> 4) << 4);
#pragma unroll
        for (int ks = 0; ks < 4; ks++) {
            uint32_t ah[2][4], al[2][4];
#pragma unroll
            for (int mt = 0; mt < 2; mt++) {
                int r = wm * 32 + mt * 16 + lrow;
                uint32_t bo = sw128((uint32_t)(r * 128 + ks * 32) + lcol);
                ldsm_x4(ah[mt], Ah_b + bo);
                ldsm_x4(al[mt], Al_b + bo);
            }
            uint32_t bh[4][4], bl[4][4];
#pragma unroll
            for (int p = 0; p < 4; p++) {
                int r = wn * 64 + p * 16 + lrow;
                uint32_t bo = sw128((uint32_t)(r * 128 + ks * 32) + lcol);
                ldsm_x4(bh[p], Bh_b + bo);
                ldsm_x4(bl[p], Bl_b + bo);
            }
#pragma unroll
            for (int mt = 0; mt < 2; mt++)
#pragma unroll
                for (int p = 0; p < 4; p++) {
#pragma unroll
                    for (int q = 0; q < 2; q++) {
                        int nt = p * 2 + q;
                        mma16816(acc[mt][nt], ah[mt], bh[p][q], bh[p][q + 2]);
                        mma16816(acc[mt][nt], ah[mt], bl[p][q], bl[p][q + 2]);
                        mma16816(acc[mt][nt], al[mt], bh[p][q], bh[p][q + 2]);
                    }
                }
        }
        __syncthreads();
    }
}

// ---------------- xW = emb[labels] @ W_ih^T + b_ih + b_hh (mma) ------------
__global__ __launch_bounds__(256) void k_xw_mma(const int* __restrict__ labels,
                                                const float* __restrict__ b_ih,
                                                const float* __restrict__ b_hh) {
    extern __shared__ char smraw[];
    __shared__ int rowlab[128];
    uint32_t sb = (smem_u32(smraw) + 1023u) & ~1023u;
    int tid = threadIdx.x, warp = tid >> 5, lane = tid & 31;
    int n0 = blockIdx.x * 128, m0 = blockIdx.y * 128;
    if (tid < 128) {
        int m = m0 + tid;
        int lab = labels[(m & 63) * T + (m >> 6)];
        rowlab[tid] = lab < 0 ? 0 : (lab >= V ? V - 1 : lab);
    }
    __syncthreads();
    auto issue = [&](int c, int stage) {
        uint32_t sbase = sb + stage * LG_STAGE_BYTES;
#pragma unroll
        for (int i = 0; i < 16; i++) {
            int slot = i * 256 + tid;
            int comp = slot >> 10, w = slot & 1023;
            int r = w >> 3, ch = w & 7;
            const __half* src;
            if (comp == 0)      src = g_embh + (size_t)rowlab[r] * D;
            else if (comp == 1) src = g_embl + (size_t)rowlab[r] * D;
            else if (comp == 2) src = g_wih_h + (size_t)(n0 + r) * D;
            else                src = g_wih_l + (size_t)(n0 + r) * D;
            src += c * LG_KC + ch * 8;
            uint32_t dst = sbase + comp * LG_COMP_BYTES + sw128(r * 128 + ch * 16);
            CP_ASYNC16(dst, src);
        }
        CP_COMMIT();
    };
    float acc[2][8][4] = {};
    mma_tile_128<D / LG_KC>(sb, issue, acc, warp, lane);
    int wm = warp & 3, wn = warp >> 2;
#pragma unroll
    for (int mt = 0; mt < 2; mt++) {
        int mrow = m0 + wm * 32 + mt * 16 + (lane >> 2);
#pragma unroll
        for (int nt = 0; nt < 8; nt++) {
            int n = n0 + wn * 64 + nt * 8 + (lane & 3) * 2;
            float2 bi = *(const float2*)(b_ih + n);
            float2 bh2 = *(const float2*)(b_hh + n);
            float2 o0 = {acc[mt][nt][0] + bi.x + bh2.x, acc[mt][nt][1] + bi.y + bh2.y};
            float2 o1 = {acc[mt][nt][2] + bi.x + bh2.x, acc[mt][nt][3] + bi.y + bh2.y};
            *(float2*)(g_xw + (size_t)mrow * GD + n) = o0;
            *(float2*)(g_xw + (size_t)(mrow + 8) * GD + n) = o1;
        }
    }
}

// ---------------- gates partials via mma: C[b, gatedim] k-split -------------
#define GT_COMP_BYTES (64 * 128)
__global__ __launch_bounds__(256) void k_gates_mma(int t) {
    __shared__ __align__(1024) char sm[4 * GT_COMP_BYTES];
    uint32_t sb = smem_u32(sm);
    int tid = threadIdx.x, warp = tid >> 5, lane = tid & 31;
    int n0 = blockIdx.x * 64;
    int kb = blockIdx.y * 64;
    int wm = warp & 1, wn = warp >> 1;
    const __half* srcs[4] = {g_hh16, g_hl16,
                             g_whh_h + (size_t)n0 * D, g_whh_l + (size_t)n0 * D};
#pragma unroll
    for (int i = 0; i < 8; i++) {
        int slot = i * 256 + tid;
        int comp = slot >> 9, w = slot & 511;
        int r = w >> 3, ch = w & 7;
        const __half* src = srcs[comp] + (size_t)r * D + kb + ch * 8;
        uint32_t dst = sb + comp * GT_COMP_BYTES + sw128(r * 128 + ch * 16);
        CP_ASYNC16(dst, src);
    }
    CP_COMMIT();
    CP_WAIT(0);
    __syncthreads();
    uint32_t Ah_b = sb, Al_b = sb + GT_COMP_BYTES;
    uint32_t Bh_b = sb + 2 * GT_COMP_BYTES, Bl_b = sb + 3 * GT_COMP_BYTES;
    int lrow = lane & 15;
    uint32_t lcol = (uint32_t)((lane >> 4) << 4);
    float acc[2][2][4] = {};
#pragma unroll
    for (int ks = 0; ks < 4; ks++) {
        uint32_t ah[2][4], al[2][4];
#pragma unroll
        for (int mt = 0; mt < 2; mt++) {
            int r = wm * 32 + mt * 16 + lrow;
            uint32_t bo = sw128((uint32_t)(r * 128 + ks * 32) + lcol);
            ldsm_x4(ah[mt], Ah_b + bo);
            ldsm_x4(al[mt], Al_b + bo);
        }
        uint32_t bh[4], bl[4];
        {
            int r = wn * 16 + lrow;
            uint32_t bo = sw128((uint32_t)(r * 128 + ks * 32) + lcol);
            ldsm_x4(bh, Bh_b + bo);
            ldsm_x4(bl, Bl_b + bo);
        }
#pragma unroll
        for (int mt = 0; mt < 2; mt++)
#pragma unroll
            for (int q = 0; q < 2; q++) {
                mma16816(acc[mt][q], ah[mt], bh[q], bh[q + 2]);
                mma16816(acc[mt][q], ah[mt], bl[q], bl[q + 2]);
                mma16816(acc[mt][q], al[mt], bh[q], bh[q + 2]);
            }
    }
    float* base = g_gpart + (size_t)blockIdx.y * B * GD;
#pragma unroll
    for (int mt = 0; mt < 2; mt++) {
        int br = wm * 32 + mt * 16 + (lane >> 2);
#pragma unroll
        for (int q = 0; q < 2; q++) {
            int n = n0 + wn * 16 + q * 8 + (lane & 3) * 2;
            float2 o0 = {acc[mt][q][0], acc[mt][q][1]};
            float2 o1 = {acc[mt][q][2], acc[mt][q][3]};
            *(float2*)(base + (size_t)br * GD + n) = o0;
            *(float2*)(base + (size_t)(br + 8) * GD + n) = o1;
        }
    }
}

// ======= fused step, cluster pair per b: cell + scores + softmax + ctx ======
// grid 128 (cluster 2): b = blk>>1, half = blk&1. 512 threads.
// cell redundant; scores s-half; DSMEM score exchange; softmax redundant;
// ctx d-half using fp16 feats.
__global__ __launch_bounds__(512) __cluster_dims__(2, 1, 1)
void k_step2(int t, const float* __restrict__ feats) {
    __shared__ __align__(16) float hs[D];
    __shared__ __align__(16) float wall[S];
    __shared__ float red[256];
    __shared__ __align__(16) float2 csum2[4][128];
    int tid = threadIdx.x;
    int b = blockIdx.x >> 1, half = blockIdx.x & 1;
    int peer = half ^ 1;

    // Phase 1: LSTM cell (redundant on both CTAs of the pair)
    {
        int d = tid;
        const float* c_in = g_cbuf + (t & 1) * (B * D);
        float* c_out = g_cbuf + ((t + 1) & 1) * (B * D);
        const float* xwrow = g_xw + ((size_t)t * B + b) * GD;
        float ig = xwrow[d], fg = xwrow[D + d], gg = xwrow[2 * D + d], og = xwrow[3 * D + d];
#pragma unroll
        for (int ks = 0; ks < 8; ks++) {
            const float* gp = g_gpart + ((size_t)ks * B + b) * GD;
            ig += gp[d];
            fg += gp[D + d];
            gg += gp[2 * D + d];
            og += gp[3 * D + d];
        }
        float cn = sigf(fg) * c_in[b * D + d] + sigf(ig) * tanhf(gg);
        float hv = sigf(og) * tanhf(cn);
        hs[d] = hv;
        if (half == 0) {
            c_out[b * D + d] = cn;
            __half hh = __float2half_rn(hv);
            __half hl = __float2half_rn(hv - __half2float(hh));
            g_hh16[b * D + d] = hh;
            g_hl16[b * D + d] = hl;
            size_t mrow = (size_t)t * B + b;
            g_hcinh[mrow * 2 * D + d] = hh;
            g_hcinl[mrow * 2 * D + d] = hl;
        }
    }
    __syncthreads();

    // Phase 2: scores for s in [half*128, half*128+128), 16 warps x 8 s
    int warp = tid >> 5, lane = tid & 31;
    const float4* h4 = (const float4*)hs;
#pragma unroll
    for (int i = 0; i < 8; i++) {
        int s = half * 128 + warp * 8 + i;
        const float4* f4 = (const float4*)(feats + ((size_t)s * B + b) * D);
        float a = 0.f;
#pragma unroll
        for (int j = 0; j < 4; j++) {
            int ii = j * 32 + lane;
            float4 f = f4[ii], h = h4[ii];
            a = fmaf(f.x, h.x, fmaf(f.y, h.y, fmaf(f.z, h.z, fmaf(f.w, h.w, a))));
        }
#pragma unroll
        for (int o = 16; o; o >>= 1) a += __shfl_xor_sync(0xffffffffu, a, o);
        if (lane == 0) {
            wall[s] = a;
            dsmem_st_f32(smem_u32(&wall[s]), peer, a);
        }
    }
    CLUSTER_SYNC();   // peer scores visible in wall

    // Phase 3: softmax over wall[0..255] (redundant per CTA)
    float sv = (tid < S) ? wall[tid] : -1e30f;
    if (tid < 256) red[tid] = sv;
    __syncthreads();
    for (int st = 128; st; st >>= 1) {
        if (tid < st) red[tid] = fmaxf(red[tid], red[tid + st]);
        __syncthreads();
    }
    float mx = red[0];
    __syncthreads();
    float e = 0.f;
    if (tid < S) {
        e = expf(sv - mx);
        red[tid] = e;
    }
    __syncthreads();
    for (int st = 128; st; st >>= 1) {
        if (tid < st) red[tid] += red[tid + st];
        __syncthreads();
    }
    if (tid < S) wall[tid] = e / red[0];
    __syncthreads();

    // Phase 4: ctx for d in [half*256, half*256+256), fp16 feats, 4 s-shards
    {
        int p = tid & 127, shard = tid >> 7;
        float2 a = {0.f, 0.f};
#pragma unroll 8
        for (int i = 0; i < 64; i++) {
            int s = shard * 64 + i;
            __half2 f = *((const __half2*)(g_feats16 + ((size_t)s * B + b) * D + half * 256) + p);
            float2 ff = __half22float2(f);
            float w = wall[s];
            a.x = fmaf(w, ff.x, a.x);
            a.y = fmaf(w, ff.y, a.y);
        }
        csum2[shard][p] = a;
        __syncthreads();
        if (tid < 128) {
            float2 c0 = csum2[0][tid], c1 = csum2[1][tid];
            float2 c2 = csum2[2][tid], c3 = csum2[3][tid];
            float cx = c0.x + c1.x + c2.x + c3.x;
            float cy = c0.y + c1.y + c2.y + c3.y;
            __half hx = __float2half_rn(cx), hy = __float2half_rn(cy);
            __half2 ph = {hx, hy};
            __half2 pl = {__float2half_rn(cx - __half2float(hx)),
                          __float2half_rn(cy - __half2float(hy))};
            size_t mrow = (size_t)t * B + b;
            size_t off = mrow * 2 * D + D + half * 256 + 2 * tid;
            *(__half2*)&g_hcinh[off] = ph;
            *(__half2*)&g_hcinl[off] = pl;
        }
    }
}

// ---------------- hcall = [h, ctx] @ W_hc^T + b_hc (mma) --------------------
__global__ __launch_bounds__(256) void k_hc_mma(const float* __restrict__ b_hc) {
    extern __shared__ char smraw[];
    uint32_t sb = (smem_u32(smraw) + 1023u) & ~1023u;
    int tid = threadIdx.x, warp = tid >> 5, lane = tid & 31;
    int n0 = blockIdx.x * 128, m0 = blockIdx.y * 128;
    auto issue = [&](int c, int stage) {
        uint32_t sbase = sb + stage * LG_STAGE_BYTES;
#pragma unroll
        for (int i = 0; i < 16; i++) {
            int slot = i * 256 + tid;
            int comp = slot >> 10, w = slot & 1023;
            int r = w >> 3, ch = w & 7;
            const __half* src;
            if (comp == 0)      src = g_hcinh + (size_t)(m0 + r) * 2 * D;
            else if (comp == 1) src = g_hcinl + (size_t)(m0 + r) * 2 * D;
            else if (comp == 2) src = g_whc_h + (size_t)(n0 + r) * 2 * D;
            else                src = g_whc_l + (size_t)(n0 + r) * 2 * D;
            src += c * LG_KC + ch * 8;
            uint32_t dst = sbase + comp * LG_COMP_BYTES + sw128(r * 128 + ch * 16);
            CP_ASYNC16(dst, src);
        }
        CP_COMMIT();
    };
    float acc[2][8][4] = {};
    mma_tile_128<2 * D / LG_KC>(sb, issue, acc, warp, lane);
    int wm = warp & 3, wn = warp >> 2;
#pragma unroll
    for (int mt = 0; mt < 2; mt++) {
        int mrow = m0 + wm * 32 + mt * 16 + (lane >> 2);
#pragma unroll
        for (int nt = 0; nt < 8; nt++) {
            int n = n0 + wn * 64 + nt * 8 + (lane & 3) * 2;
            float2 bv = *(const float2*)(b_hc + n);
            float2 o0 = {acc[mt][nt][0] + bv.x, acc[mt][nt][1] + bv.y};
            float2 o1 = {acc[mt][nt][2] + bv.x, acc[mt][nt][3] + bv.y};
            *(float2*)(g_hcall + (size_t)mrow * D + n) = o0;
            *(float2*)(g_hcall + (size_t)(mrow + 8) * D + n) = o1;
        }
    }
}

// ---------------- LayerNorm + tanh -> pe (fp16 hi/lo, fused) ---------------
__global__ __launch_bounds__(128) void k_ln_all(const float* __restrict__ ln_g,
                                                const float* __restrict__ ln_b) {
    int m = blockIdx.x;
    int tid = threadIdx.x;
    __shared__ float wsum[4];
    float4 x = *(const float4*)(g_hcall + (size_t)m * D + tid * 4);
    float s = x.x + x.y + x.z + x.w;
#pragma unroll
    for (int o = 16; o; o >>= 1) s += __shfl_xor_sync(0xffffffff, s, o);
    if ((tid & 31) == 0) wsum[tid >> 5] = s;
    __syncthreads();
    float mean = (wsum[0] + wsum[1] + wsum[2] + wsum[3]) * (1.f / D);
    float4 dv = {x.x - mean, x.y - mean, x.z - mean, x.w - mean};
    float v = dv.x * dv.x + dv.y * dv.y + dv.z * dv.z + dv.w * dv.w;
#pragma unroll
    for (int o = 16; o; o >>= 1) v += __shfl_xor_sync(0xffffffff, v, o);
    __syncthreads();
    if ((tid & 31) == 0) wsum[tid >> 5] = v;
    __syncthreads();
    float var = (wsum[0] + wsum[1] + wsum[2] + wsum[3]) * (1.f / D);
    float rs = rsqrtf(var + 1e-5f);
    float4 gl = *(const float4*)(ln_g + tid * 4);
    float4 bl = *(const float4*)(ln_b + tid * 4);
    float y0 = tanhf(fmaf(gl.x, dv.x * rs, bl.x));
    float y1 = tanhf(fmaf(gl.y, dv.y * rs, bl.y));
    float y2 = tanhf(fmaf(gl.z, dv.z * rs, bl.z));
    float y3 = tanhf(fmaf(gl.w, dv.w * rs, bl.w));
    __half h0 = __float2half_rn(y0), h1 = __float2half_rn(y1);
    __half h2 = __float2half_rn(y2), h3 = __float2half_rn(y3);
    size_t o = (size_t)m * D + tid * 4;
    *(__half2*)&g_peh[o] = {h0, h1};
    *(__half2*)&g_peh[o + 2] = {h2, h3};
    *(__half2*)&g_pel[o] = {__float2half_rn(y0 - __half2float(h0)),
                            __float2half_rn(y1 - __half2float(h1))};
    *(__half2*)&g_pel[o + 2] = {__float2half_rn(y2 - __half2float(h2)),
                                __float2half_rn(y3 - __half2float(h3))};
}

// ============ logits via mma.sync fp16 hi/lo split ==========================
__global__ __launch_bounds__(256) void k_logits_mma(const float* __restrict__ vbias,
                                                    float* __restrict__ out) {
    extern __shared__ char smraw[];
    uint32_t sb = (smem_u32(smraw) + 1023u) & ~1023u;
    int tid = threadIdx.x, warp = tid >> 5, lane = tid & 31;
    int m0 = blockIdx.x * 128, n0 = blockIdx.y * 128;
    const __half* srcs[4] = {g_peh + (size_t)m0 * D, g_pel + (size_t)m0 * D,
                             g_embh + (size_t)n0 * D, g_embl + (size_t)n0 * D};
    auto issue = [&](int c, int stage) {
        uint32_t sbase = sb + stage * LG_STAGE_BYTES;
#pragma unroll
        for (int i = 0; i < 16; i++) {
            int slot = i * 256 + tid;
            int comp = slot >> 10, w = slot & 1023;
            int r = w >> 3, ch = w & 7;
            const __half* src = srcs[comp] + (size_t)r * D + c * LG_KC + ch * 8;
            uint32_t dst = sbase + comp * LG_COMP_BYTES + sw128(r * 128 + ch * 16);
            CP_ASYNC16(dst, src);
        }
        CP_COMMIT();
    };
    float acc[2][8][4] = {};
    mma_tile_128<D / LG_KC>(sb, issue, acc, warp, lane);
    int wm = warp & 3, wn = warp >> 2;
#pragma unroll
    for (int mt = 0; mt < 2; mt++) {
        int mrow = m0 + wm * 32 + mt * 16 + (lane >> 2);
#pragma unroll
        for (int nt = 0; nt < 8; nt++) {
            int n = n0 + wn * 64 + nt * 8 + (lane & 3) * 2;
            float2 bv = *(const float2*)(vbias + n);
            float2 o0 = {acc[mt][nt][0] + bv.x, acc[mt][nt][1] + bv.y};
            float2 o1 = {acc[mt][nt][2] + bv.x, acc[mt][nt][3] + bv.y};
            *(float2*)(out + (size_t)mrow * V + n) = o0;
            *(float2*)(out + (size_t)(mrow + 8) * V + n) = o1;
        }
    }
}

// ---------------- launch ----------------------------------------------------
extern "C" void kernel_launch(void* const* d_in, const int* in_sizes, int n_in,
                              void* d_out, int out_size) {
    const float* feats = (const float*)d_in[0];
    const int* labels = (const int*)d_in[1];
    const float* W_ih = (const float*)d_in[2];
    const float* W_hh = (const float*)d_in[3];
    const float* b_ih = (const float*)d_in[4];
    const float* b_hh = (const float*)d_in[5];
    const float* W_hc = (const float*)d_in[6];
    const float* b_hc = (const float*)d_in[7];
    const float* ln_g = (const float*)d_in[8];
    const float* ln_b = (const float*)d_in[9];
    const float* emb = (const float*)d_in[10];
    const float* vbias = (const float*)d_in[11];
    float* out = (float*)d_out;

    cudaFuncSetAttribute(k_logits_mma, cudaFuncAttributeMaxDynamicSharedMemorySize,
                         LG_SMEM_REQ);
    cudaFuncSetAttribute(k_xw_mma, cudaFuncAttributeMaxDynamicSharedMemorySize,
                         LG_SMEM_REQ);
    cudaFuncSetAttribute(k_hc_mma, cudaFuncAttributeMaxDynamicSharedMemorySize,
                         LG_SMEM_REQ);

    __half *embh, *embl, *whhh, *whhl, *wihh, *wihl, *whch, *whcl, *f16;
    cudaGetSymbolAddress((void**)&embh, g_embh);
    cudaGetSymbolAddress((void**)&embl, g_embl);
    cudaGetSymbolAddress((void**)&whhh, g_whh_h);
    cudaGetSymbolAddress((void**)&whhl, g_whh_l);
    cudaGetSymbolAddress((void**)&wihh, g_wih_h);
    cudaGetSymbolAddress((void**)&wihl, g_wih_l);
    cudaGetSymbolAddress((void**)&whch, g_whc_h);
    cudaGetSymbolAddress((void**)&whcl, g_whc_l);
    cudaGetSymbolAddress((void**)&f16, g_feats16);

    k_init<<<(B * D) / 256, 256>>>(feats);
    k_cvt<<<(V * D / 4) / 256, 256>>>(emb, embh, embl);
    k_cvt<<<(GD * D / 4) / 256, 256>>>(W_hh, whhh, whhl);
    k_cvt<<<(GD * D / 4) / 256, 256>>>(W_ih, wihh, wihl);
    k_cvt<<<(D * 2 * D / 4) / 256, 256>>>(W_hc, whch, whcl);
    k_cvt1<<<((size_t)S * B * D / 4) / 256, 256>>>(feats, f16);
    k_xw_mma<<<dim3(GD / 128, (T * B) / 128), 256, LG_SMEM_REQ>>>(labels, b_ih, b_hh);
    for (int t = 0; t < T; t++) {
        k_gates_mma<<<dim3(GD / 64, D / 64), 256>>>(t);
        k_step2<<<2 * B, 512>>>(t, feats);
    }
    k_hc_mma<<<dim3(D / 128, (T * B) / 128), 256, LG_SMEM_REQ>>>(b_hc);
    k_ln_all<<<T * B, 128>>>(ln_g, ln_b);
    k_logits_mma<<<dim3((T * B) / 128, V / 128), 256, LG_SMEM_REQ>>>(vbias, out);
}

// round 13
// speedup vs baseline: 1.1780x; 1.0419x over previous
#include <cuda_runtime.h>
#include <cuda_fp16.h>
#include <math.h>
#include <cstdint>

#define S 256
#define B 64
#define D 512
#define T 64
#define V 32000
#define GD 2048  /* 4*D */

// ---------------- scratch (device globals; no runtime allocation) ----------
__device__ float g_xw[(size_t)T * B * GD];        // x@W_ih^T + b_ih + b_hh
__device__ float g_cbuf[2 * B * D];               // double-buffered cell state
__device__ float g_gpart[4 * B * GD];             // k-split partial gate sums
__device__ float g_scraw[B * S];                  // raw scores for current step
__device__ float g_hcall[(size_t)T * B * D];      // hc pre-LN
__device__ __half g_feats16[(size_t)S * B * D];   // feats in fp16 (ctx only)
__device__ __half g_peh[(size_t)T * B * D];
__device__ __half g_pel[(size_t)T * B * D];
__device__ __half g_embh[(size_t)V * D];
__device__ __half g_embl[(size_t)V * D];
__device__ __half g_whh_h[(size_t)GD * D];
__device__ __half g_whh_l[(size_t)GD * D];
__device__ __half g_wih_h[(size_t)GD * D];
__device__ __half g_wih_l[(size_t)GD * D];
__device__ __half g_whc_h[(size_t)D * 2 * D];
__device__ __half g_whc_l[(size_t)D * 2 * D];
__device__ __half g_hh16[B * D];                  // current h, fp16 hi
__device__ __half g_hl16[B * D];                  // current h, fp16 lo
__device__ __half g_hcinh[(size_t)T * B * 2 * D]; // [h|ctx] hi, [4096,1024]
__device__ __half g_hcinl[(size_t)T * B * 2 * D]; // [h|ctx] lo

__device__ __forceinline__ float sigf(float x) { return 1.f / (1.f + expf(-x)); }

// ======================= PTX helpers ========================================
__device__ __forceinline__ uint32_t smem_u32(const void* p) {
    uint32_t a;
    asm("{ .reg .u64 t; cvta.to.shared.u64 t, %1; cvt.u32.u64 %0, t; }" : "=r"(a) : "l"(p));
    return a;
}
__device__ __forceinline__ uint32_t sw128(uint32_t off) { return off ^ ((off >> 3) & 0x70); }

#define CP_ASYNC16(dst, src) \
    asm volatile("cp.async.cg.shared.global [%0], [%1], 16;" :: "r"(dst), "l"(src) : "memory")
#define CP_COMMIT() asm volatile("cp.async.commit_group;" ::: "memory")
#define CP_WAIT(n) asm volatile("cp.async.wait_group %0;" :: "n"(n) : "memory")

__device__ __forceinline__ void ldsm_x4(uint32_t* r, uint32_t addr) {
    asm volatile("ldmatrix.sync.aligned.m8n8.x4.shared.b16 {%0,%1,%2,%3}, [%4];"
                 : "=r"(r[0]), "=r"(r[1]), "=r"(r[2]), "=r"(r[3]) : "r"(addr));
}
__device__ __forceinline__ void mma16816(float* c, const uint32_t* a, uint32_t b0, uint32_t b1) {
    asm volatile(
        "mma.sync.aligned.m16n8k16.row.col.f32.f16.f16.f32 "
        "{%0,%1,%2,%3}, {%4,%5,%6,%7}, {%8,%9}, {%0,%1,%2,%3};"
        : "+f"(c[0]), "+f"(c[1]), "+f"(c[2]), "+f"(c[3])
        : "r"(a[0]), "r"(a[1]), "r"(a[2]), "r"(a[3]), "r"(b0), "r"(b1));
}

// ---------------- init h0 = c0 = feats[S-1] --------------------------------
__global__ void k_init(const float* __restrict__ feats) {
    int i = blockIdx.x * blockDim.x + threadIdx.x;
    float v = feats[(size_t)(S - 1) * B * D + i];
    g_cbuf[i] = v;                      // buffer 0
    __half hh = __float2half_rn(v);
    g_hh16[i] = hh;
    g_hl16[i] = __float2half_rn(v - __half2float(hh));
}

// ---------------- fp32 -> fp16 hi/lo converter ------------------------------
__global__ void k_cvt(const float* __restrict__ src, __half* __restrict__ dh,
                      __half* __restrict__ dl) {
    int i = blockIdx.x * blockDim.x + threadIdx.x;
    float4 x = ((const float4*)src)[i];
    __half h0 = __float2half_rn(x.x), h1 = __float2half_rn(x.y);
    __half h2 = __float2half_rn(x.z), h3 = __float2half_rn(x.w);
    __half2 ph0 = {h0, h1}, ph1 = {h2, h3};
    __half2 pl0 = {__float2half_rn(x.x - __half2float(h0)),
                   __float2half_rn(x.y - __half2float(h1))};
    __half2 pl1 = {__float2half_rn(x.z - __half2float(h2)),
                   __float2half_rn(x.w - __half2float(h3))};
    ((__half2*)dh)[2 * i] = ph0;
    ((__half2*)dh)[2 * i + 1] = ph1;
    ((__half2*)dl)[2 * i] = pl0;
    ((__half2*)dl)[2 * i + 1] = pl1;
}

// ---------------- fp32 -> fp16 (single) converter ---------------------------
__global__ void k_cvt1(const float* __restrict__ src, __half* __restrict__ dh) {
    int i = blockIdx.x * blockDim.x + threadIdx.x;
    float4 x = ((const float4*)src)[i];
    __half2 p0 = {__float2half_rn(x.x), __float2half_rn(x.y)};
    __half2 p1 = {__float2half_rn(x.z), __float2half_rn(x.w)};
    ((__half2*)dh)[2 * i] = p0;
    ((__half2*)dh)[2 * i + 1] = p1;
}

// ======================= shared mma tile machinery ==========================
#define LG_KC 64
#define LG_COMP_BYTES (128 * 128)
#define LG_STAGE_BYTES (4 * LG_COMP_BYTES)
#define LG_SMEM_REQ (2 * LG_STAGE_BYTES + 1024)

template <int KCH, typename ISSUE>
__device__ __forceinline__ void mma_tile_128(uint32_t sb, ISSUE issue,
                                             float (&acc)[2][8][4],
                                             int warp, int lane) {
    int wm = warp & 3, wn = warp >> 2;
    issue(0, 0);
    for (int c = 0; c < KCH; c++) {
        if (c + 1 < KCH) {
            issue(c + 1, (c + 1) & 1);
            CP_WAIT(1);
        } else {
            CP_WAIT(0);
        }
        __syncthreads();
        uint32_t st = sb + (c & 1) * LG_STAGE_BYTES;
        uint32_t Ah_b = st, Al_b = st + LG_COMP_BYTES;
        uint32_t Bh_b = st + 2 * LG_COMP_BYTES, Bl_b = st + 3 * LG_COMP_BYTES;
        int lrow = lane & 15;
        uint32_t lcol = (uint32_t)((lane >> 4) << 4);
#pragma unroll
        for (int ks = 0; ks < 4; ks++) {
            uint32_t ah[2][4], al[2][4];
#pragma unroll
            for (int mt = 0; mt < 2; mt++) {
                int r = wm * 32 + mt * 16 + lrow;
                uint32_t bo = sw128((uint32_t)(r * 128 + ks * 32) + lcol);
                ldsm_x4(ah[mt], Ah_b + bo);
                ldsm_x4(al[mt], Al_b + bo);
            }
            uint32_t bh[4][4], bl[4][4];
#pragma unroll
            for (int p = 0; p < 4; p++) {
                int r = wn * 64 + p * 16 + lrow;
                uint32_t bo = sw128((uint32_t)(r * 128 + ks * 32) + lcol);
                ldsm_x4(bh[p], Bh_b + bo);
                ldsm_x4(bl[p], Bl_b + bo);
            }
#pragma unroll
            for (int mt = 0; mt < 2; mt++)
#pragma unroll
                for (int p = 0; p < 4; p++) {
#pragma unroll
                    for (int q = 0; q < 2; q++) {
                        int nt = p * 2 + q;
                        mma16816(acc[mt][nt], ah[mt], bh[p][q], bh[p][q + 2]);
                        mma16816(acc[mt][nt], ah[mt], bl[p][q], bl[p][q + 2]);
                        mma16816(acc[mt][nt], al[mt], bh[p][q], bh[p][q + 2]);
                    }
                }
        }
        __syncthreads();
    }
}

// ---------------- xW = emb[labels] @ W_ih^T + b_ih + b_hh (mma) ------------
__global__ __launch_bounds__(256) void k_xw_mma(const int* __restrict__ labels,
                                                const float* __restrict__ b_ih,
                                                const float* __restrict__ b_hh) {
    extern __shared__ char smraw[];
    __shared__ int rowlab[128];
    uint32_t sb = (smem_u32(smraw) + 1023u) & ~1023u;
    int tid = threadIdx.x, warp = tid >> 5, lane = tid & 31;
    int n0 = blockIdx.x * 128, m0 = blockIdx.y * 128;
    if (tid < 128) {
        int m = m0 + tid;
        int lab = labels[(m & 63) * T + (m >> 6)];
        rowlab[tid] = lab < 0 ? 0 : (lab >= V ? V - 1 : lab);
    }
    __syncthreads();
    auto issue = [&](int c, int stage) {
        uint32_t sbase = sb + stage * LG_STAGE_BYTES;
#pragma unroll
        for (int i = 0; i < 16; i++) {
            int slot = i * 256 + tid;
            int comp = slot >> 10, w = slot & 1023;
            int r = w >> 3, ch = w & 7;
            const __half* src;
            if (comp == 0)      src = g_embh + (size_t)rowlab[r] * D;
            else if (comp == 1) src = g_embl + (size_t)rowlab[r] * D;
            else if (comp == 2) src = g_wih_h + (size_t)(n0 + r) * D;
            else                src = g_wih_l + (size_t)(n0 + r) * D;
            src += c * LG_KC + ch * 8;
            uint32_t dst = sbase + comp * LG_COMP_BYTES + sw128(r * 128 + ch * 16);
            CP_ASYNC16(dst, src);
        }
        CP_COMMIT();
    };
    float acc[2][8][4] = {};
    mma_tile_128<D / LG_KC>(sb, issue, acc, warp, lane);
    int wm = warp & 3, wn = warp >> 2;
#pragma unroll
    for (int mt = 0; mt < 2; mt++) {
        int mrow = m0 + wm * 32 + mt * 16 + (lane >> 2);
#pragma unroll
        for (int nt = 0; nt < 8; nt++) {
            int n = n0 + wn * 64 + nt * 8 + (lane & 3) * 2;
            float2 bi = *(const float2*)(b_ih + n);
            float2 bh2 = *(const float2*)(b_hh + n);
            float2 o0 = {acc[mt][nt][0] + bi.x + bh2.x, acc[mt][nt][1] + bi.y + bh2.y};
            float2 o1 = {acc[mt][nt][2] + bi.x + bh2.x, acc[mt][nt][3] + bi.y + bh2.y};
            *(float2*)(g_xw + (size_t)mrow * GD + n) = o0;
            *(float2*)(g_xw + (size_t)(mrow + 8) * GD + n) = o1;
        }
    }
}

// ---------------- gates partial mma body (K=128 split, 256 thr) -------------
// cta_n in [0,32), ksplit in [0,4). Writes gpart[ksplit].
#define GT_COMP_BYTES (64 * 128)
__device__ __forceinline__ void gates_body(char* sm, int cta_n, int ksplit) {
    uint32_t sb = smem_u32(sm);
    int tid = threadIdx.x, warp = tid >> 5, lane = tid & 31;
    int n0 = cta_n * 64;
    int wm = warp & 1, wn = warp >> 1;
    int lrow = lane & 15;
    uint32_t lcol = (uint32_t)((lane >> 4) << 4);
    float acc[2][2][4] = {};
#pragma unroll
    for (int sub = 0; sub < 2; sub++) {
        int kb = ksplit * 128 + sub * 64;
        const __half* srcs[4] = {g_hh16, g_hl16,
                                 g_whh_h + (size_t)n0 * D, g_whh_l + (size_t)n0 * D};
#pragma unroll
        for (int i = 0; i < 8; i++) {
            int slot = i * 256 + tid;
            int comp = slot >> 9, w = slot & 511;
            int r = w >> 3, ch = w & 7;
            const __half* src = srcs[comp] + (size_t)r * D + kb + ch * 8;
            uint32_t dst = sb + comp * GT_COMP_BYTES + sw128(r * 128 + ch * 16);
            CP_ASYNC16(dst, src);
        }
        CP_COMMIT();
        CP_WAIT(0);
        __syncthreads();
        uint32_t Ah_b = sb, Al_b = sb + GT_COMP_BYTES;
        uint32_t Bh_b = sb + 2 * GT_COMP_BYTES, Bl_b = sb + 3 * GT_COMP_BYTES;
#pragma unroll
        for (int ks = 0; ks < 4; ks++) {
            uint32_t ah[2][4], al[2][4];
#pragma unroll
            for (int mt = 0; mt < 2; mt++) {
                int r = wm * 32 + mt * 16 + lrow;
                uint32_t bo = sw128((uint32_t)(r * 128 + ks * 32) + lcol);
                ldsm_x4(ah[mt], Ah_b + bo);
                ldsm_x4(al[mt], Al_b + bo);
            }
            uint32_t bh[4], bl[4];
            {
                int r = wn * 16 + lrow;
                uint32_t bo = sw128((uint32_t)(r * 128 + ks * 32) + lcol);
                ldsm_x4(bh, Bh_b + bo);
                ldsm_x4(bl, Bl_b + bo);
            }
#pragma unroll
            for (int mt = 0; mt < 2; mt++)
#pragma unroll
                for (int q = 0; q < 2; q++) {
                    mma16816(acc[mt][q], ah[mt], bh[q], bh[q + 2]);
                    mma16816(acc[mt][q], ah[mt], bl[q], bl[q + 2]);
                    mma16816(acc[mt][q], al[mt], bh[q], bh[q + 2]);
                }
        }
        __syncthreads();
    }
    float* base = g_gpart + (size_t)ksplit * B * GD;
#pragma unroll
    for (int mt = 0; mt < 2; mt++) {
        int br = wm * 32 + mt * 16 + (lane >> 2);
#pragma unroll
        for (int q = 0; q < 2; q++) {
            int n = n0 + wn * 16 + q * 8 + (lane & 3) * 2;
            float2 o0 = {acc[mt][q][0], acc[mt][q][1]};
            float2 o1 = {acc[mt][q][2], acc[mt][q][3]};
            *(float2*)(base + (size_t)br * GD + n) = o0;
            *(float2*)(base + (size_t)(br + 8) * GD + n) = o1;
        }
    }
}

// standalone gates (for t=0): grid (32, 4)
__global__ __launch_bounds__(256) void k_gates4() {
    __shared__ __align__(1024) char sm[4 * GT_COMP_BYTES];
    gates_body(sm, blockIdx.x, blockIdx.y);
}

// ======= cell + scores (grid 128 pairs, 512 thr) ============================
__global__ __launch_bounds__(512) void k_cellsc(int t, const float* __restrict__ feats) {
    __shared__ __align__(16) float hs[D];
    int tid = threadIdx.x;
    int b = blockIdx.x >> 1, half = blockIdx.x & 1;

    // Phase 1: LSTM cell (redundant per pair)
    {
        int d = tid;
        const float* c_in = g_cbuf + (t & 1) * (B * D);
        float* c_out = g_cbuf + ((t + 1) & 1) * (B * D);
        const float* xwrow = g_xw + ((size_t)t * B + b) * GD;
        float ig = xwrow[d], fg = xwrow[D + d], gg = xwrow[2 * D + d], og = xwrow[3 * D + d];
#pragma unroll
        for (int ks = 0; ks < 4; ks++) {
            const float* gp = g_gpart + ((size_t)ks * B + b) * GD;
            ig += gp[d];
            fg += gp[D + d];
            gg += gp[2 * D + d];
            og += gp[3 * D + d];
        }
        float cn = sigf(fg) * c_in[b * D + d] + sigf(ig) * tanhf(gg);
        float hv = sigf(og) * tanhf(cn);
        hs[d] = hv;
        if (half == 0) {
            c_out[b * D + d] = cn;
            __half hh = __float2half_rn(hv);
            __half hl = __float2half_rn(hv - __half2float(hh));
            g_hh16[b * D + d] = hh;
            g_hl16[b * D + d] = hl;
            size_t mrow = (size_t)t * B + b;
            g_hcinh[mrow * 2 * D + d] = hh;
            g_hcinl[mrow * 2 * D + d] = hl;
        }
    }
    __syncthreads();

    // Phase 2: scores for s in [half*128, +128): 16 warps x 8 s -> global
    int warp = tid >> 5, lane = tid & 31;
    const float4* h4 = (const float4*)hs;
#pragma unroll
    for (int i = 0; i < 8; i++) {
        int s = half * 128 + warp * 8 + i;
        const float4* f4 = (const float4*)(feats + ((size_t)s * B + b) * D);
        float a = 0.f;
#pragma unroll
        for (int j = 0; j < 4; j++) {
            int ii = j * 32 + lane;
            float4 f = f4[ii], h = h4[ii];
            a = fmaf(f.x, h.x, fmaf(f.y, h.y, fmaf(f.z, h.z, fmaf(f.w, h.w, a))));
        }
#pragma unroll
        for (int o = 16; o; o >>= 1) a += __shfl_xor_sync(0xffffffffu, a, o);
        if (lane == 0) g_scraw[b * S + s] = a;
    }
}

// ======= heterogeneous: softmax+ctx(t) [CTAs 0-127] | gates(t+1) [128-255] ==
__global__ __launch_bounds__(256) void k_mix(int t) {
    __shared__ __align__(1024) char sm[4 * GT_COMP_BYTES];
    int tid = threadIdx.x;
    if (blockIdx.x >= 128) {
        if (t + 1 >= T) return;
        int cta = blockIdx.x - 128;
        gates_body(sm, cta & 31, cta >> 5);
        return;
    }
    // ---- attention: softmax + ctx for (b, half) ----
    float* wall = (float*)sm;                 // 256 floats
    float* red = (float*)(sm + 1024);         // 256 floats
    float2* csum2 = (float2*)(sm + 2048);     // [2][128] float2
    int b = blockIdx.x >> 1, half = blockIdx.x & 1;

    float sv = g_scraw[b * S + tid];
    red[tid] = sv;
    __syncthreads();
    for (int st = 128; st; st >>= 1) {
        if (tid < st) red[tid] = fmaxf(red[tid], red[tid + st]);
        __syncthreads();
    }
    float mx = red[0];
    __syncthreads();
    float e = expf(sv - mx);
    red[tid] = e;
    __syncthreads();
    for (int st = 128; st; st >>= 1) {
        if (tid < st) red[tid] += red[tid + st];
        __syncthreads();
    }
    wall[tid] = e / red[0];
    __syncthreads();

    // ctx: d-half (256 dims = 128 half2), 2 s-shards of 128
    {
        int p = tid & 127, shard = tid >> 7;
        float2 a = {0.f, 0.f};
#pragma unroll 8
        for (int i = 0; i < 128; i++) {
            int s = shard * 128 + i;
            __half2 f = *((const __half2*)(g_feats16 + ((size_t)s * B + b) * D + half * 256) + p);
            float2 ff = __half22float2(f);
            float w = wall[s];
            a.x = fmaf(w, ff.x, a.x);
            a.y = fmaf(w, ff.y, a.y);
        }
        csum2[shard * 128 + p] = a;
        __syncthreads();
        if (tid < 128) {
            float2 c0 = csum2[tid], c1 = csum2[128 + tid];
            float cx = c0.x + c1.x, cy = c0.y + c1.y;
            __half hx = __float2half_rn(cx), hy = __float2half_rn(cy);
            __half2 ph = {hx, hy};
            __half2 pl = {__float2half_rn(cx - __half2float(hx)),
                          __float2half_rn(cy - __half2float(hy))};
            size_t mrow = (size_t)t * B + b;
            size_t off = mrow * 2 * D + D + half * 256 + 2 * tid;
            *(__half2*)&g_hcinh[off] = ph;
            *(__half2*)&g_hcinl[off] = pl;
        }
    }
}

// ---------------- hcall = [h, ctx] @ W_hc^T + b_hc (mma) --------------------
__global__ __launch_bounds__(256) void k_hc_mma(const float* __restrict__ b_hc) {
    extern __shared__ char smraw[];
    uint32_t sb = (smem_u32(smraw) + 1023u) & ~1023u;
    int tid = threadIdx.x, warp = tid >> 5, lane = tid & 31;
    int n0 = blockIdx.x * 128, m0 = blockIdx.y * 128;
    auto issue = [&](int c, int stage) {
        uint32_t sbase = sb + stage * LG_STAGE_BYTES;
#pragma unroll
        for (int i = 0; i < 16; i++) {
            int slot = i * 256 + tid;
            int comp = slot >> 10, w = slot & 1023;
            int r = w >> 3, ch = w & 7;
            const __half* src;
            if (comp == 0)      src = g_hcinh + (size_t)(m0 + r) * 2 * D;
            else if (comp == 1) src = g_hcinl + (size_t)(m0 + r) * 2 * D;
            else if (comp == 2) src = g_whc_h + (size_t)(n0 + r) * 2 * D;
            else                src = g_whc_l + (size_t)(n0 + r) * 2 * D;
            src += c * LG_KC + ch * 8;
            uint32_t dst = sbase + comp * LG_COMP_BYTES + sw128(r * 128 + ch * 16);
            CP_ASYNC16(dst, src);
        }
        CP_COMMIT();
    };
    float acc[2][8][4] = {};
    mma_tile_128<2 * D / LG_KC>(sb, issue, acc, warp, lane);
    int wm = warp & 3, wn = warp >> 2;
#pragma unroll
    for (int mt = 0; mt < 2; mt++) {
        int mrow = m0 + wm * 32 + mt * 16 + (lane >> 2);
#pragma unroll
        for (int nt = 0; nt < 8; nt++) {
            int n = n0 + wn * 64 + nt * 8 + (lane & 3) * 2;
            float2 bv = *(const float2*)(b_hc + n);
            float2 o0 = {acc[mt][nt][0] + bv.x, acc[mt][nt][1] + bv.y};
            float2 o1 = {acc[mt][nt][2] + bv.x, acc[mt][nt][3] + bv.y};
            *(float2*)(g_hcall + (size_t)mrow * D + n) = o0;
            *(float2*)(g_hcall + (size_t)(mrow + 8) * D + n) = o1;
        }
    }
}

// ---------------- LayerNorm + tanh -> pe (fp16 hi/lo, fused) ---------------
__global__ __launch_bounds__(128) void k_ln_all(const float* __restrict__ ln_g,
                                                const float* __restrict__ ln_b) {
    int m = blockIdx.x;
    int tid = threadIdx.x;
    __shared__ float wsum[4];
    float4 x = *(const float4*)(g_hcall + (size_t)m * D + tid * 4);
    float s = x.x + x.y + x.z + x.w;
#pragma unroll
    for (int o = 16; o; o >>= 1) s += __shfl_xor_sync(0xffffffff, s, o);
    if ((tid & 31) == 0) wsum[tid >> 5] = s;
    __syncthreads();
    float mean = (wsum[0] + wsum[1] + wsum[2] + wsum[3]) * (1.f / D);
    float4 dv = {x.x - mean, x.y - mean, x.z - mean, x.w - mean};
    float v = dv.x * dv.x + dv.y * dv.y + dv.z * dv.z + dv.w * dv.w;
#pragma unroll
    for (int o = 16; o; o >>= 1) v += __shfl_xor_sync(0xffffffff, v, o);
    __syncthreads();
    if ((tid & 31) == 0) wsum[tid >> 5] = v;
    __syncthreads();
    float var = (wsum[0] + wsum[1] + wsum[2] + wsum[3]) * (1.f / D);
    float rs = rsqrtf(var + 1e-5f);
    float4 gl = *(const float4*)(ln_g + tid * 4);
    float4 bl = *(const float4*)(ln_b + tid * 4);
    float y0 = tanhf(fmaf(gl.x, dv.x * rs, bl.x));
    float y1 = tanhf(fmaf(gl.y, dv.y * rs, bl.y));
    float y2 = tanhf(fmaf(gl.z, dv.z * rs, bl.z));
    float y3 = tanhf(fmaf(gl.w, dv.w * rs, bl.w));
    __half h0 = __float2half_rn(y0), h1 = __float2half_rn(y1);
    __half h2 = __float2half_rn(y2), h3 = __float2half_rn(y3);
    size_t o = (size_t)m * D + tid * 4;
    *(__half2*)&g_peh[o] = {h0, h1};
    *(__half2*)&g_peh[o + 2] = {h2, h3};
    *(__half2*)&g_pel[o] = {__float2half_rn(y0 - __half2float(h0)),
                            __float2half_rn(y1 - __half2float(h1))};
    *(__half2*)&g_pel[o + 2] = {__float2half_rn(y2 - __half2float(h2)),
                                __float2half_rn(y3 - __half2float(h3))};
}

// ============ logits via mma.sync fp16 hi/lo split ==========================
__global__ __launch_bounds__(256) void k_logits_mma(const float* __restrict__ vbias,
                                                    float* __restrict__ out) {
    extern __shared__ char smraw[];
    uint32_t sb = (smem_u32(smraw) + 1023u) & ~1023u;
    int tid = threadIdx.x, warp = tid >> 5, lane = tid & 31;
    int m0 = blockIdx.x * 128, n0 = blockIdx.y * 128;
    const __half* srcs[4] = {g_peh + (size_t)m0 * D, g_pel + (size_t)m0 * D,
                             g_embh + (size_t)n0 * D, g_embl + (size_t)n0 * D};
    auto issue = [&](int c, int stage) {
        uint32_t sbase = sb + stage * LG_STAGE_BYTES;
#pragma unroll
        for (int i = 0; i < 16; i++) {
            int slot = i * 256 + tid;
            int comp = slot >> 10, w = slot & 1023;
            int r = w >> 3, ch = w & 7;
            const __half* src = srcs[comp] + (size_t)r * D + c * LG_KC + ch * 8;
            uint32_t dst = sbase + comp * LG_COMP_BYTES + sw128(r * 128 + ch * 16);
            CP_ASYNC16(dst, src);
        }
        CP_COMMIT();
    };
    float acc[2][8][4] = {};
    mma_tile_128<D / LG_KC>(sb, issue, acc, warp, lane);
    int wm = warp & 3, wn = warp >> 2;
#pragma unroll
    for (int mt = 0; mt < 2; mt++) {
        int mrow = m0 + wm * 32 + mt * 16 + (lane >> 2);
#pragma unroll
        for (int nt = 0; nt < 8; nt++) {
            int n = n0 + wn * 64 + nt * 8 + (lane & 3) * 2;
            float2 bv = *(const float2*)(vbias + n);
            float2 o0 = {acc[mt][nt][0] + bv.x, acc[mt][nt][1] + bv.y};
            float2 o1 = {acc[mt][nt][2] + bv.x, acc[mt][nt][3] + bv.y};
            *(float2*)(out + (size_t)mrow * V + n) = o0;
            *(float2*)(out + (size_t)(mrow + 8) * V + n) = o1;
        }
    }
}

// ---------------- launch ----------------------------------------------------
extern "C" void kernel_launch(void* const* d_in, const int* in_sizes, int n_in,
                              void* d_out, int out_size) {
    const float* feats = (const float*)d_in[0];
    const int* labels = (const int*)d_in[1];
    const float* W_ih = (const float*)d_in[2];
    const float* W_hh = (const float*)d_in[3];
    const float* b_ih = (const float*)d_in[4];
    const float* b_hh = (const float*)d_in[5];
    const float* W_hc = (const float*)d_in[6];
    const float* b_hc = (const float*)d_in[7];
    const float* ln_g = (const float*)d_in[8];
    const float* ln_b = (const float*)d_in[9];
    const float* emb = (const float*)d_in[10];
    const float* vbias = (const float*)d_in[11];
    float* out = (float*)d_out;

    cudaFuncSetAttribute(k_logits_mma, cudaFuncAttributeMaxDynamicSharedMemorySize,
                         LG_SMEM_REQ);
    cudaFuncSetAttribute(k_xw_mma, cudaFuncAttributeMaxDynamicSharedMemorySize,
                         LG_SMEM_REQ);
    cudaFuncSetAttribute(k_hc_mma, cudaFuncAttributeMaxDynamicSharedMemorySize,
                         LG_SMEM_REQ);

    __half *embh, *embl, *whhh, *whhl, *wihh, *wihl, *whch, *whcl, *f16;
    cudaGetSymbolAddress((void**)&embh, g_embh);
    cudaGetSymbolAddress((void**)&embl, g_embl);
    cudaGetSymbolAddress((void**)&whhh, g_whh_h);
    cudaGetSymbolAddress((void**)&whhl, g_whh_l);
    cudaGetSymbolAddress((void**)&wihh, g_wih_h);
    cudaGetSymbolAddress((void**)&wihl, g_wih_l);
    cudaGetSymbolAddress((void**)&whch, g_whc_h);
    cudaGetSymbolAddress((void**)&whcl, g_whc_l);
    cudaGetSymbolAddress((void**)&f16, g_feats16);

    k_init<<<(B * D) / 256, 256>>>(feats);
    k_cvt<<<(V * D / 4) / 256, 256>>>(emb, embh, embl);
    k_cvt<<<(GD * D / 4) / 256, 256>>>(W_hh, whhh, whhl);
    k_cvt<<<(GD * D / 4) / 256, 256>>>(W_ih, wihh, wihl);
    k_cvt<<<(D * 2 * D / 4) / 256, 256>>>(W_hc, whch, whcl);
    k_cvt1<<<((size_t)S * B * D / 4) / 256, 256>>>(feats, f16);
    k_xw_mma<<<dim3(GD / 128, (T * B) / 128), 256, LG_SMEM_REQ>>>(labels, b_ih, b_hh);
    k_gates4<<<dim3(32, 4), 256>>>();   // gates for t=0 from h0
    for (int t = 0; t < T; t++) {
        k_cellsc<<<2 * B, 512>>>(t, feats);
        k_mix<<<256, 256>>>(t);         // attn(t) || gates(t+1)
    }
    k_hc_mma<<<dim3(D / 128, (T * B) / 128), 256, LG_SMEM_REQ>>>(b_hc);
    k_ln_all<<<T * B, 128>>>(ln_g, ln_b);
    k_logits_mma<<<dim3((T * B) / 128, V / 128), 256, LG_SMEM_REQ>>>(vbias, out);
}

// round 14
// speedup vs baseline: 1.3801x; 1.1716x over previous
#include <cuda_runtime.h>
#include <cuda_fp16.h>
#include <math.h>
#include <cstdint>

#define S 256
#define B 64
#define D 512
#define T 64
#define V 32000
#define GD 2048  /* 4*D */

// ---------------- scratch (device globals; no runtime allocation) ----------
__device__ float g_xw[(size_t)T * B * GD];        // x@W_ih^T + b_ih + b_hh
__device__ float g_cbuf[2 * B * D];               // double-buffered cell state
__device__ float g_gpart[4 * B * GD];             // k-split partial gate sums
__device__ float g_scraw[B * S];                  // raw scores for current step
__device__ float g_hcall[(size_t)T * B * D];      // hc pre-LN
__device__ __half g_feats16[(size_t)S * B * D];   // feats in fp16 (ctx only)
__device__ __half g_peh[(size_t)T * B * D];
__device__ __half g_pel[(size_t)T * B * D];
__device__ __half g_embh[(size_t)V * D];
__device__ __half g_embl[(size_t)V * D];
__device__ __half g_whh_h[(size_t)GD * D];
__device__ __half g_whh_l[(size_t)GD * D];
__device__ __half g_wih_h[(size_t)GD * D];
__device__ __half g_wih_l[(size_t)GD * D];
__device__ __half g_whc_h[(size_t)D * 2 * D];
__device__ __half g_whc_l[(size_t)D * 2 * D];
__device__ __half g_hh16[B * D];                  // current h, fp16 hi
__device__ __half g_hl16[B * D];                  // current h, fp16 lo
__device__ __half g_hcinh[(size_t)T * B * 2 * D]; // [h|ctx] hi, [4096,1024]
__device__ __half g_hcinl[(size_t)T * B * 2 * D]; // [h|ctx] lo

__device__ __forceinline__ float sigf(float x) { return 1.f / (1.f + expf(-x)); }

// ======================= PTX helpers ========================================
__device__ __forceinline__ uint32_t smem_u32(const void* p) {
    uint32_t a;
    asm("{ .reg .u64 t; cvta.to.shared.u64 t, %1; cvt.u32.u64 %0, t; }" : "=r"(a) : "l"(p));
    return a;
}
__device__ __forceinline__ uint32_t sw128(uint32_t off) { return off ^ ((off >> 3) & 0x70); }

#define CP_ASYNC16(dst, src) \
    asm volatile("cp.async.cg.shared.global [%0], [%1], 16;" :: "r"(dst), "l"(src) : "memory")
#define CP_COMMIT() asm volatile("cp.async.commit_group;" ::: "memory")
#define CP_WAIT(n) asm volatile("cp.async.wait_group %0;" :: "n"(n) : "memory")

__device__ __forceinline__ void ldsm_x4(uint32_t* r, uint32_t addr) {
    asm volatile("ldmatrix.sync.aligned.m8n8.x4.shared.b16 {%0,%1,%2,%3}, [%4];"
                 : "=r"(r[0]), "=r"(r[1]), "=r"(r[2]), "=r"(r[3]) : "r"(addr));
}
__device__ __forceinline__ void mma16816(float* c, const uint32_t* a, uint32_t b0, uint32_t b1) {
    asm volatile(
        "mma.sync.aligned.m16n8k16.row.col.f32.f16.f16.f32 "
        "{%0,%1,%2,%3}, {%4,%5,%6,%7}, {%8,%9}, {%0,%1,%2,%3};"
        : "+f"(c[0]), "+f"(c[1]), "+f"(c[2]), "+f"(c[3])
        : "r"(a[0]), "r"(a[1]), "r"(a[2]), "r"(a[3]), "r"(b0), "r"(b1));
}

// ---------------- init h0 = c0 = feats[S-1] --------------------------------
__global__ void k_init(const float* __restrict__ feats) {
    int i = blockIdx.x * blockDim.x + threadIdx.x;
    float v = feats[(size_t)(S - 1) * B * D + i];
    g_cbuf[i] = v;                      // buffer 0
    __half hh = __float2half_rn(v);
    g_hh16[i] = hh;
    g_hl16[i] = __float2half_rn(v - __half2float(hh));
}

// ---------------- fp32 -> fp16 hi/lo converter ------------------------------
__global__ void k_cvt(const float* __restrict__ src, __half* __restrict__ dh,
                      __half* __restrict__ dl) {
    int i = blockIdx.x * blockDim.x + threadIdx.x;
    float4 x = ((const float4*)src)[i];
    __half h0 = __float2half_rn(x.x), h1 = __float2half_rn(x.y);
    __half h2 = __float2half_rn(x.z), h3 = __float2half_rn(x.w);
    __half2 ph0 = {h0, h1}, ph1 = {h2, h3};
    __half2 pl0 = {__float2half_rn(x.x - __half2float(h0)),
                   __float2half_rn(x.y - __half2float(h1))};
    __half2 pl1 = {__float2half_rn(x.z - __half2float(h2)),
                   __float2half_rn(x.w - __half2float(h3))};
    ((__half2*)dh)[2 * i] = ph0;
    ((__half2*)dh)[2 * i + 1] = ph1;
    ((__half2*)dl)[2 * i] = pl0;
    ((__half2*)dl)[2 * i + 1] = pl1;
}

// ---------------- fp32 -> fp16 (single) converter ---------------------------
__global__ void k_cvt1(const float* __restrict__ src, __half* __restrict__ dh) {
    int i = blockIdx.x * blockDim.x + threadIdx.x;
    float4 x = ((const float4*)src)[i];
    __half2 p0 = {__float2half_rn(x.x), __float2half_rn(x.y)};
    __half2 p1 = {__float2half_rn(x.z), __float2half_rn(x.w)};
    ((__half2*)dh)[2 * i] = p0;
    ((__half2*)dh)[2 * i + 1] = p1;
}

// ======================= shared mma tile machinery ==========================
#define LG_KC 64
#define LG_COMP_BYTES (128 * 128)
#define LG_STAGE_BYTES (4 * LG_COMP_BYTES)
#define LG_SMEM_REQ (2 * LG_STAGE_BYTES + 1024)
// 2-product logits variant: 3 components per stage
#define LT_STAGE_BYTES (3 * LG_COMP_BYTES)
#define LT_SMEM_REQ (2 * LT_STAGE_BYTES + 1024)

template <int KCH, typename ISSUE>
__device__ __forceinline__ void mma_tile_128(uint32_t sb, ISSUE issue,
                                             float (&acc)[2][8][4],
                                             int warp, int lane) {
    int wm = warp & 3, wn = warp >> 2;
    issue(0, 0);
    for (int c = 0; c < KCH; c++) {
        if (c + 1 < KCH) {
            issue(c + 1, (c + 1) & 1);
            CP_WAIT(1);
        } else {
            CP_WAIT(0);
        }
        __syncthreads();
        uint32_t st = sb + (c & 1) * LG_STAGE_BYTES;
        uint32_t Ah_b = st, Al_b = st + LG_COMP_BYTES;
        uint32_t Bh_b = st + 2 * LG_COMP_BYTES, Bl_b = st + 3 * LG_COMP_BYTES;
        int lrow = lane & 15;
        uint32_t lcol = (uint32_t)((lane >> 4) << 4);
#pragma unroll
        for (int ks = 0; ks < 4; ks++) {
            uint32_t ah[2][4], al[2][4];
#pragma unroll
            for (int mt = 0; mt < 2; mt++) {
                int r = wm * 32 + mt * 16 + lrow;
                uint32_t bo = sw128((uint32_t)(r * 128 + ks * 32) + lcol);
                ldsm_x4(ah[mt], Ah_b + bo);
                ldsm_x4(al[mt], Al_b + bo);
            }
            uint32_t bh[4][4], bl[4][4];
#pragma unroll
            for (int p = 0; p < 4; p++) {
                int r = wn * 64 + p * 16 + lrow;
                uint32_t bo = sw128((uint32_t)(r * 128 + ks * 32) + lcol);
                ldsm_x4(bh[p], Bh_b + bo);
                ldsm_x4(bl[p], Bl_b + bo);
            }
#pragma unroll
            for (int mt = 0; mt < 2; mt++)
#pragma unroll
                for (int p = 0; p < 4; p++) {
#pragma unroll
                    for (int q = 0; q < 2; q++) {
                        int nt = p * 2 + q;
                        mma16816(acc[mt][nt], ah[mt], bh[p][q], bh[p][q + 2]);
                        mma16816(acc[mt][nt], ah[mt], bl[p][q], bl[p][q + 2]);
                        mma16816(acc[mt][nt], al[mt], bh[p][q], bh[p][q + 2]);
                    }
                }
        }
        __syncthreads();
    }
}

// ---------------- xW = emb[labels] @ W_ih^T + b_ih + b_hh (mma) ------------
__global__ __launch_bounds__(256) void k_xw_mma(const int* __restrict__ labels,
                                                const float* __restrict__ b_ih,
                                                const float* __restrict__ b_hh) {
    extern __shared__ char smraw[];
    __shared__ int rowlab[128];
    uint32_t sb = (smem_u32(smraw) + 1023u) & ~1023u;
    int tid = threadIdx.x, warp = tid >> 5, lane = tid & 31;
    int n0 = blockIdx.x * 128, m0 = blockIdx.y * 128;
    if (tid < 128) {
        int m = m0 + tid;
        int lab = labels[(m & 63) * T + (m >> 6)];
        rowlab[tid] = lab < 0 ? 0 : (lab >= V ? V - 1 : lab);
    }
    __syncthreads();
    auto issue = [&](int c, int stage) {
        uint32_t sbase = sb + stage * LG_STAGE_BYTES;
#pragma unroll
        for (int i = 0; i < 16; i++) {
            int slot = i * 256 + tid;
            int comp = slot >> 10, w = slot & 1023;
            int r = w >> 3, ch = w & 7;
            const __half* src;
            if (comp == 0)      src = g_embh + (size_t)rowlab[r] * D;
            else if (comp == 1) src = g_embl + (size_t)rowlab[r] * D;
            else if (comp == 2) src = g_wih_h + (size_t)(n0 + r) * D;
            else                src = g_wih_l + (size_t)(n0 + r) * D;
            src += c * LG_KC + ch * 8;
            uint32_t dst = sbase + comp * LG_COMP_BYTES + sw128(r * 128 + ch * 16);
            CP_ASYNC16(dst, src);
        }
        CP_COMMIT();
    };
    float acc[2][8][4] = {};
    mma_tile_128<D / LG_KC>(sb, issue, acc, warp, lane);
    int wm = warp & 3, wn = warp >> 2;
#pragma unroll
    for (int mt = 0; mt < 2; mt++) {
        int mrow = m0 + wm * 32 + mt * 16 + (lane >> 2);
#pragma unroll
        for (int nt = 0; nt < 8; nt++) {
            int n = n0 + wn * 64 + nt * 8 + (lane & 3) * 2;
            float2 bi = *(const float2*)(b_ih + n);
            float2 bh2 = *(const float2*)(b_hh + n);
            float2 o0 = {acc[mt][nt][0] + bi.x + bh2.x, acc[mt][nt][1] + bi.y + bh2.y};
            float2 o1 = {acc[mt][nt][2] + bi.x + bh2.x, acc[mt][nt][3] + bi.y + bh2.y};
            *(float2*)(g_xw + (size_t)mrow * GD + n) = o0;
            *(float2*)(g_xw + (size_t)(mrow + 8) * GD + n) = o1;
        }
    }
}

// ---------------- gates partial mma body (K=128 split, 256 thr) -------------
#define GT_COMP_BYTES (64 * 128)
__device__ __forceinline__ void gates_body(char* sm, int cta_n, int ksplit) {
    uint32_t sb = smem_u32(sm);
    int tid = threadIdx.x, warp = tid >> 5, lane = tid & 31;
    int n0 = cta_n * 64;
    int wm = warp & 1, wn = warp >> 1;
    int lrow = lane & 15;
    uint32_t lcol = (uint32_t)((lane >> 4) << 4);
    float acc[2][2][4] = {};
#pragma unroll
    for (int sub = 0; sub < 2; sub++) {
        int kb = ksplit * 128 + sub * 64;
        const __half* srcs[4] = {g_hh16, g_hl16,
                                 g_whh_h + (size_t)n0 * D, g_whh_l + (size_t)n0 * D};
#pragma unroll
        for (int i = 0; i < 8; i++) {
            int slot = i * 256 + tid;
            int comp = slot >> 9, w = slot & 511;
            int r = w >> 3, ch = w & 7;
            const __half* src = srcs[comp] + (size_t)r * D + kb + ch * 8;
            uint32_t dst = sb + comp * GT_COMP_BYTES + sw128(r * 128 + ch * 16);
            CP_ASYNC16(dst, src);
        }
        CP_COMMIT();
        CP_WAIT(0);
        __syncthreads();
        uint32_t Ah_b = sb, Al_b = sb + GT_COMP_BYTES;
        uint32_t Bh_b = sb + 2 * GT_COMP_BYTES, Bl_b = sb + 3 * GT_COMP_BYTES;
#pragma unroll
        for (int ks = 0; ks < 4; ks++) {
            uint32_t ah[2][4], al[2][4];
#pragma unroll
            for (int mt = 0; mt < 2; mt++) {
                int r = wm * 32 + mt * 16 + lrow;
                uint32_t bo = sw128((uint32_t)(r * 128 + ks * 32) + lcol);
                ldsm_x4(ah[mt], Ah_b + bo);
                ldsm_x4(al[mt], Al_b + bo);
            }
            uint32_t bh[4], bl[4];
            {
                int r = wn * 16 + lrow;
                uint32_t bo = sw128((uint32_t)(r * 128 + ks * 32) + lcol);
                ldsm_x4(bh, Bh_b + bo);
                ldsm_x4(bl, Bl_b + bo);
            }
#pragma unroll
            for (int mt = 0; mt < 2; mt++)
#pragma unroll
                for (int q = 0; q < 2; q++) {
                    mma16816(acc[mt][q], ah[mt], bh[q], bh[q + 2]);
                    mma16816(acc[mt][q], ah[mt], bl[q], bl[q + 2]);
                    mma16816(acc[mt][q], al[mt], bh[q], bh[q + 2]);
                }
        }
        __syncthreads();
    }
    float* base = g_gpart + (size_t)ksplit * B * GD;
#pragma unroll
    for (int mt = 0; mt < 2; mt++) {
        int br = wm * 32 + mt * 16 + (lane >> 2);
#pragma unroll
        for (int q = 0; q < 2; q++) {
            int n = n0 + wn * 16 + q * 8 + (lane & 3) * 2;
            float2 o0 = {acc[mt][q][0], acc[mt][q][1]};
            float2 o1 = {acc[mt][q][2], acc[mt][q][3]};
            *(float2*)(base + (size_t)br * GD + n) = o0;
            *(float2*)(base + (size_t)(br + 8) * GD + n) = o1;
        }
    }
}

// standalone gates (for t=0): grid (32, 4)
__global__ __launch_bounds__(256) void k_gates4() {
    __shared__ __align__(1024) char sm[4 * GT_COMP_BYTES];
    gates_body(sm, blockIdx.x, blockIdx.y);
}

// ======= cell + scores (grid 128 pairs, 512 thr) ============================
__global__ __launch_bounds__(512) void k_cellsc(int t, const float* __restrict__ feats) {
    __shared__ __align__(16) float hs[D];
    int tid = threadIdx.x;
    int b = blockIdx.x >> 1, half = blockIdx.x & 1;

    // Phase 1: LSTM cell (redundant per pair)
    {
        int d = tid;
        const float* c_in = g_cbuf + (t & 1) * (B * D);
        float* c_out = g_cbuf + ((t + 1) & 1) * (B * D);
        const float* xwrow = g_xw + ((size_t)t * B + b) * GD;
        float ig = xwrow[d], fg = xwrow[D + d], gg = xwrow[2 * D + d], og = xwrow[3 * D + d];
#pragma unroll
        for (int ks = 0; ks < 4; ks++) {
            const float* gp = g_gpart + ((size_t)ks * B + b) * GD;
            ig += gp[d];
            fg += gp[D + d];
            gg += gp[2 * D + d];
            og += gp[3 * D + d];
        }
        float cn = sigf(fg) * c_in[b * D + d] + sigf(ig) * tanhf(gg);
        float hv = sigf(og) * tanhf(cn);
        hs[d] = hv;
        if (half == 0) {
            c_out[b * D + d] = cn;
            __half hh = __float2half_rn(hv);
            __half hl = __float2half_rn(hv - __half2float(hh));
            g_hh16[b * D + d] = hh;
            g_hl16[b * D + d] = hl;
            size_t mrow = (size_t)t * B + b;
            g_hcinh[mrow * 2 * D + d] = hh;
            g_hcinl[mrow * 2 * D + d] = hl;
        }
    }
    __syncthreads();

    // Phase 2: scores for s in [half*128, +128): 16 warps x 8 s -> global
    int warp = tid >> 5, lane = tid & 31;
    const float4* h4 = (const float4*)hs;
#pragma unroll
    for (int i = 0; i < 8; i++) {
        int s = half * 128 + warp * 8 + i;
        const float4* f4 = (const float4*)(feats + ((size_t)s * B + b) * D);
        float a = 0.f;
#pragma unroll
        for (int j = 0; j < 4; j++) {
            int ii = j * 32 + lane;
            float4 f = f4[ii], h = h4[ii];
            a = fmaf(f.x, h.x, fmaf(f.y, h.y, fmaf(f.z, h.z, fmaf(f.w, h.w, a))));
        }
#pragma unroll
        for (int o = 16; o; o >>= 1) a += __shfl_xor_sync(0xffffffffu, a, o);
        if (lane == 0) g_scraw[b * S + s] = a;
    }
}

// ======= heterogeneous: softmax+ctx(t) [CTAs 0-127] | gates(t+1) [128-255] ==
__global__ __launch_bounds__(256) void k_mix(int t) {
    __shared__ __align__(1024) char sm[4 * GT_COMP_BYTES];
    int tid = threadIdx.x;
    if (blockIdx.x >= 128) {
        if (t + 1 >= T) return;
        int cta = blockIdx.x - 128;
        gates_body(sm, cta & 31, cta >> 5);
        return;
    }
    // ---- attention: softmax + ctx for (b, half) ----
    float* wall = (float*)sm;                 // 256 floats
    float* red = (float*)(sm + 1024);         // 256 floats
    float2* csum2 = (float2*)(sm + 2048);     // [2][128] float2
    int b = blockIdx.x >> 1, half = blockIdx.x & 1;

    float sv = g_scraw[b * S + tid];
    red[tid] = sv;
    __syncthreads();
    for (int st = 128; st; st >>= 1) {
        if (tid < st) red[tid] = fmaxf(red[tid], red[tid + st]);
        __syncthreads();
    }
    float mx = red[0];
    __syncthreads();
    float e = expf(sv - mx);
    red[tid] = e;
    __syncthreads();
    for (int st = 128; st; st >>= 1) {
        if (tid < st) red[tid] += red[tid + st];
        __syncthreads();
    }
    wall[tid] = e / red[0];
    __syncthreads();

    // ctx: d-half (256 dims = 128 half2), 2 s-shards of 128
    {
        int p = tid & 127, shard = tid >> 7;
        float2 a = {0.f, 0.f};
#pragma unroll 8
        for (int i = 0; i < 128; i++) {
            int s = shard * 128 + i;
            __half2 f = *((const __half2*)(g_feats16 + ((size_t)s * B + b) * D + half * 256) + p);
            float2 ff = __half22float2(f);
            float w = wall[s];
            a.x = fmaf(w, ff.x, a.x);
            a.y = fmaf(w, ff.y, a.y);
        }
        csum2[shard * 128 + p] = a;
        __syncthreads();
        if (tid < 128) {
            float2 c0 = csum2[tid], c1 = csum2[128 + tid];
            float cx = c0.x + c1.x, cy = c0.y + c1.y;
            __half hx = __float2half_rn(cx), hy = __float2half_rn(cy);
            __half2 ph = {hx, hy};
            __half2 pl = {__float2half_rn(cx - __half2float(hx)),
                          __float2half_rn(cy - __half2float(hy))};
            size_t mrow = (size_t)t * B + b;
            size_t off = mrow * 2 * D + D + half * 256 + 2 * tid;
            *(__half2*)&g_hcinh[off] = ph;
            *(__half2*)&g_hcinl[off] = pl;
        }
    }
}

// ---------------- hcall = [h, ctx] @ W_hc^T + b_hc (mma) --------------------
__global__ __launch_bounds__(256) void k_hc_mma(const float* __restrict__ b_hc) {
    extern __shared__ char smraw[];
    uint32_t sb = (smem_u32(smraw) + 1023u) & ~1023u;
    int tid = threadIdx.x, warp = tid >> 5, lane = tid & 31;
    int n0 = blockIdx.x * 128, m0 = blockIdx.y * 128;
    auto issue = [&](int c, int stage) {
        uint32_t sbase = sb + stage * LG_STAGE_BYTES;
#pragma unroll
        for (int i = 0; i < 16; i++) {
            int slot = i * 256 + tid;
            int comp = slot >> 10, w = slot & 1023;
            int r = w >> 3, ch = w & 7;
            const __half* src;
            if (comp == 0)      src = g_hcinh + (size_t)(m0 + r) * 2 * D;
            else if (comp == 1) src = g_hcinl + (size_t)(m0 + r) * 2 * D;
            else if (comp == 2) src = g_whc_h + (size_t)(n0 + r) * 2 * D;
            else                src = g_whc_l + (size_t)(n0 + r) * 2 * D;
            src += c * LG_KC + ch * 8;
            uint32_t dst = sbase + comp * LG_COMP_BYTES + sw128(r * 128 + ch * 16);
            CP_ASYNC16(dst, src);
        }
        CP_COMMIT();
    };
    float acc[2][8][4] = {};
    mma_tile_128<2 * D / LG_KC>(sb, issue, acc, warp, lane);
    int wm = warp & 3, wn = warp >> 2;
#pragma unroll
    for (int mt = 0; mt < 2; mt++) {
        int mrow = m0 + wm * 32 + mt * 16 + (lane >> 2);
#pragma unroll
        for (int nt = 0; nt < 8; nt++) {
            int n = n0 + wn * 64 + nt * 8 + (lane & 3) * 2;
            float2 bv = *(const float2*)(b_hc + n);
            float2 o0 = {acc[mt][nt][0] + bv.x, acc[mt][nt][1] + bv.y};
            float2 o1 = {acc[mt][nt][2] + bv.x, acc[mt][nt][3] + bv.y};
            *(float2*)(g_hcall + (size_t)mrow * D + n) = o0;
            *(float2*)(g_hcall + (size_t)(mrow + 8) * D + n) = o1;
        }
    }
}

// ---------------- LayerNorm + tanh -> pe (fp16 hi/lo, fused) ---------------
__global__ __launch_bounds__(128) void k_ln_all(const float* __restrict__ ln_g,
                                                const float* __restrict__ ln_b) {
    int m = blockIdx.x;
    int tid = threadIdx.x;
    __shared__ float wsum[4];
    float4 x = *(const float4*)(g_hcall + (size_t)m * D + tid * 4);
    float s = x.x + x.y + x.z + x.w;
#pragma unroll
    for (int o = 16; o; o >>= 1) s += __shfl_xor_sync(0xffffffff, s, o);
    if ((tid & 31) == 0) wsum[tid >> 5] = s;
    __syncthreads();
    float mean = (wsum[0] + wsum[1] + wsum[2] + wsum[3]) * (1.f / D);
    float4 dv = {x.x - mean, x.y - mean, x.z - mean, x.w - mean};
    float v = dv.x * dv.x + dv.y * dv.y + dv.z * dv.z + dv.w * dv.w;
#pragma unroll
    for (int o = 16; o; o >>= 1) v += __shfl_xor_sync(0xffffffff, v, o);
    __syncthreads();
    if ((tid & 31) == 0) wsum[tid >> 5] = v;
    __syncthreads();
    float var = (wsum[0] + wsum[1] + wsum[2] + wsum[3]) * (1.f / D);
    float rs = rsqrtf(var + 1e-5f);
    float4 gl = *(const float4*)(ln_g + tid * 4);
    float4 bl = *(const float4*)(ln_b + tid * 4);
    float y0 = tanhf(fmaf(gl.x, dv.x * rs, bl.x));
    float y1 = tanhf(fmaf(gl.y, dv.y * rs, bl.y));
    float y2 = tanhf(fmaf(gl.z, dv.z * rs, bl.z));
    float y3 = tanhf(fmaf(gl.w, dv.w * rs, bl.w));
    __half h0 = __float2half_rn(y0), h1 = __float2half_rn(y1);
    __half h2 = __float2half_rn(y2), h3 = __float2half_rn(y3);
    size_t o = (size_t)m * D + tid * 4;
    *(__half2*)&g_peh[o] = {h0, h1};
    *(__half2*)&g_peh[o + 2] = {h2, h3};
    *(__half2*)&g_pel[o] = {__float2half_rn(y0 - __half2float(h0)),
                            __float2half_rn(y1 - __half2float(h1))};
    *(__half2*)&g_pel[o + 2] = {__float2half_rn(y2 - __half2float(h2)),
                                __float2half_rn(y3 - __half2float(h3))};
}

// ============ logits via mma.sync, 2-product hi/lo (A hi/lo x B hi) =========
// D = (pe_h + pe_l) @ emb_h^T + bias. Drops pe*emb_l (~1.4e-4 rms rel).
__global__ __launch_bounds__(256) void k_logits_mma(const float* __restrict__ vbias,
                                                    float* __restrict__ out) {
    extern __shared__ char smraw[];
    uint32_t sb = (smem_u32(smraw) + 1023u) & ~1023u;
    int tid = threadIdx.x, warp = tid >> 5, lane = tid & 31;
    int m0 = blockIdx.x * 128, n0 = blockIdx.y * 128;
    const __half* srcs[3] = {g_peh + (size_t)m0 * D, g_pel + (size_t)m0 * D,
                             g_embh + (size_t)n0 * D};
    auto issue = [&](int c, int stage) {
        uint32_t sbase = sb + stage * LT_STAGE_BYTES;
#pragma unroll
        for (int i = 0; i < 12; i++) {
            int slot = i * 256 + tid;            // 0..3071
            int comp = slot >> 10, w = slot & 1023;
            int r = w >> 3, ch = w & 7;
            const __half* src = srcs[comp] + (size_t)r * D + c * LG_KC + ch * 8;
            uint32_t dst = sbase + comp * LG_COMP_BYTES + sw128(r * 128 + ch * 16);
            CP_ASYNC16(dst, src);
        }
        CP_COMMIT();
    };
    float acc[2][8][4] = {};
    int wm = warp & 3, wn = warp >> 2;
    int lrow = lane & 15;
    uint32_t lcol = (uint32_t)((lane >> 4) << 4);
    issue(0, 0);
    for (int c = 0; c < D / LG_KC; c++) {
        if (c + 1 < D / LG_KC) {
            issue(c + 1, (c + 1) & 1);
            CP_WAIT(1);
        } else {
            CP_WAIT(0);
        }
        __syncthreads();
        uint32_t st = sb + (c & 1) * LT_STAGE_BYTES;
        uint32_t Ah_b = st, Al_b = st + LG_COMP_BYTES;
        uint32_t Bh_b = st + 2 * LG_COMP_BYTES;
#pragma unroll
        for (int ks = 0; ks < 4; ks++) {
            uint32_t ah[2][4], al[2][4];
#pragma unroll
            for (int mt = 0; mt < 2; mt++) {
                int r = wm * 32 + mt * 16 + lrow;
                uint32_t bo = sw128((uint32_t)(r * 128 + ks * 32) + lcol);
                ldsm_x4(ah[mt], Ah_b + bo);
                ldsm_x4(al[mt], Al_b + bo);
            }
            uint32_t bh[4][4];
#pragma unroll
            for (int p = 0; p < 4; p++) {
                int r = wn * 64 + p * 16 + lrow;
                uint32_t bo = sw128((uint32_t)(r * 128 + ks * 32) + lcol);
                ldsm_x4(bh[p], Bh_b + bo);
            }
#pragma unroll
            for (int mt = 0; mt < 2; mt++)
#pragma unroll
                for (int p = 0; p < 4; p++) {
#pragma unroll
                    for (int q = 0; q < 2; q++) {
                        int nt = p * 2 + q;
                        mma16816(acc[mt][nt], ah[mt], bh[p][q], bh[p][q + 2]);
                        mma16816(acc[mt][nt], al[mt], bh[p][q], bh[p][q + 2]);
                    }
                }
        }
        __syncthreads();
    }
#pragma unroll
    for (int mt = 0; mt < 2; mt++) {
        int mrow = m0 + wm * 32 + mt * 16 + (lane >> 2);
#pragma unroll
        for (int nt = 0; nt < 8; nt++) {
            int n = n0 + wn * 64 + nt * 8 + (lane & 3) * 2;
            float2 bv = *(const float2*)(vbias + n);
            float2 o0 = {acc[mt][nt][0] + bv.x, acc[mt][nt][1] + bv.y};
            float2 o1 = {acc[mt][nt][2] + bv.x, acc[mt][nt][3] + bv.y};
            *(float2*)(out + (size_t)mrow * V + n) = o0;
            *(float2*)(out + (size_t)(mrow + 8) * V + n) = o1;
        }
    }
}

// ---------------- launch ----------------------------------------------------
extern "C" void kernel_launch(void* const* d_in, const int* in_sizes, int n_in,
                              void* d_out, int out_size) {
    const float* feats = (const float*)d_in[0];
    const int* labels = (const int*)d_in[1];
    const float* W_ih = (const float*)d_in[2];
    const float* W_hh = (const float*)d_in[3];
    const float* b_ih = (const float*)d_in[4];
    const float* b_hh = (const float*)d_in[5];
    const float* W_hc = (const float*)d_in[6];
    const float* b_hc = (const float*)d_in[7];
    const float* ln_g = (const float*)d_in[8];
    const float* ln_b = (const float*)d_in[9];
    const float* emb = (const float*)d_in[10];
    const float* vbias = (const float*)d_in[11];
    float* out = (float*)d_out;

    cudaFuncSetAttribute(k_logits_mma, cudaFuncAttributeMaxDynamicSharedMemorySize,
                         LT_SMEM_REQ);
    cudaFuncSetAttribute(k_xw_mma, cudaFuncAttributeMaxDynamicSharedMemorySize,
                         LG_SMEM_REQ);
    cudaFuncSetAttribute(k_hc_mma, cudaFuncAttributeMaxDynamicSharedMemorySize,
                         LG_SMEM_REQ);

    __half *embh, *embl, *whhh, *whhl, *wihh, *wihl, *whch, *whcl, *f16;
    cudaGetSymbolAddress((void**)&embh, g_embh);
    cudaGetSymbolAddress((void**)&embl, g_embl);
    cudaGetSymbolAddress((void**)&whhh, g_whh_h);
    cudaGetSymbolAddress((void**)&whhl, g_whh_l);
    cudaGetSymbolAddress((void**)&wihh, g_wih_h);
    cudaGetSymbolAddress((void**)&wihl, g_wih_l);
    cudaGetSymbolAddress((void**)&whch, g_whc_h);
    cudaGetSymbolAddress((void**)&whcl, g_whc_l);
    cudaGetSymbolAddress((void**)&f16, g_feats16);

    k_init<<<(B * D) / 256, 256>>>(feats);
    k_cvt<<<(V * D / 4) / 256, 256>>>(emb, embh, embl);
    k_cvt<<<(GD * D / 4) / 256, 256>>>(W_hh, whhh, whhl);
    k_cvt<<<(GD * D / 4) / 256, 256>>>(W_ih, wihh, wihl);
    k_cvt<<<(D * 2 * D / 4) / 256, 256>>>(W_hc, whch, whcl);
    k_cvt1<<<((size_t)S * B * D / 4) / 256, 256>>>(feats, f16);
    k_xw_mma<<<dim3(GD / 128, (T * B) / 128), 256, LG_SMEM_REQ>>>(labels, b_ih, b_hh);
    k_gates4<<<dim3(32, 4), 256>>>();   // gates for t=0 from h0
    for (int t = 0; t < T; t++) {
        k_cellsc<<<2 * B, 512>>>(t, feats);
        k_mix<<<256, 256>>>(t);         // attn(t) || gates(t+1)
    }
    k_hc_mma<<<dim3(D / 128, (T * B) / 128), 256, LG_SMEM_REQ>>>(b_hc);
    k_ln_all<<<T * B, 128>>>(ln_g, ln_b);
    k_logits_mma<<<dim3((T * B) / 128, V / 128), 256, LT_SMEM_REQ>>>(vbias, out);
}

// round 15
// speedup vs baseline: 1.8039x; 1.3071x over previous
#include <cuda_runtime.h>
#include <cuda_fp16.h>
#include <math.h>
#include <cstdint>

#define S 256
#define B 64
#define D 512
#define T 64
#define V 32000
#define GD 2048  /* 4*D */

// ---------------- scratch (device globals; no runtime allocation) ----------
__device__ float g_xw[(size_t)T * B * GD];        // x@W_ih^T + b_ih + b_hh
__device__ float g_cbuf[2 * B * D];               // double-buffered cell state
__device__ float g_gpart[4 * B * GD];             // k-split partial gate sums
__device__ float g_scraw[B * S];                  // raw scores for current step
__device__ float g_hcall[(size_t)T * B * D];      // hc pre-LN
__device__ __half g_feats16[(size_t)S * B * D];   // feats in fp16 (ctx only)
__device__ __half g_peh[(size_t)T * B * D];
__device__ __half g_embh[(size_t)V * D];
__device__ __half g_embl[(size_t)V * D];
__device__ __half g_whh_h[(size_t)GD * D];
__device__ __half g_whh_l[(size_t)GD * D];
__device__ __half g_wih_h[(size_t)GD * D];
__device__ __half g_wih_l[(size_t)GD * D];
__device__ __half g_whc_h[(size_t)D * 2 * D];
__device__ __half g_whc_l[(size_t)D * 2 * D];
__device__ __half g_hh16[B * D];                  // current h, fp16 hi
__device__ __half g_hl16[B * D];                  // current h, fp16 lo
__device__ __half g_hcinh[(size_t)T * B * 2 * D]; // [h|ctx] hi, [4096,1024]
__device__ __half g_hcinl[(size_t)T * B * 2 * D]; // [h|ctx] lo

__device__ __forceinline__ float sigf(float x) { return 1.f / (1.f + expf(-x)); }

// ======================= PTX helpers ========================================
__device__ __forceinline__ uint32_t smem_u32(const void* p) {
    uint32_t a;
    asm("{ .reg .u64 t; cvta.to.shared.u64 t, %1; cvt.u32.u64 %0, t; }" : "=r"(a) : "l"(p));
    return a;
}
__device__ __forceinline__ uint32_t sw128(uint32_t off) { return off ^ ((off >> 3) & 0x70); }

#define CP_ASYNC16(dst, src) \
    asm volatile("cp.async.cg.shared.global [%0], [%1], 16;" :: "r"(dst), "l"(src) : "memory")
#define CP_COMMIT() asm volatile("cp.async.commit_group;" ::: "memory")
#define CP_WAIT(n) asm volatile("cp.async.wait_group %0;" :: "n"(n) : "memory")

__device__ __forceinline__ void ldsm_x4(uint32_t* r, uint32_t addr) {
    asm volatile("ldmatrix.sync.aligned.m8n8.x4.shared.b16 {%0,%1,%2,%3}, [%4];"
                 : "=r"(r[0]), "=r"(r[1]), "=r"(r[2]), "=r"(r[3]) : "r"(addr));
}
__device__ __forceinline__ void mma16816(float* c, const uint32_t* a, uint32_t b0, uint32_t b1) {
    asm volatile(
        "mma.sync.aligned.m16n8k16.row.col.f32.f16.f16.f32 "
        "{%0,%1,%2,%3}, {%4,%5,%6,%7}, {%8,%9}, {%0,%1,%2,%3};"
        : "+f"(c[0]), "+f"(c[1]), "+f"(c[2]), "+f"(c[3])
        : "r"(a[0]), "r"(a[1]), "r"(a[2]), "r"(a[3]), "r"(b0), "r"(b1));
}

// ---------------- init h0 = c0 = feats[S-1] --------------------------------
__global__ void k_init(const float* __restrict__ feats) {
    int i = blockIdx.x * blockDim.x + threadIdx.x;
    float v = feats[(size_t)(S - 1) * B * D + i];
    g_cbuf[i] = v;                      // buffer 0
    __half hh = __float2half_rn(v);
    g_hh16[i] = hh;
    g_hl16[i] = __float2half_rn(v - __half2float(hh));
}

// ---------------- fp32 -> fp16 hi/lo converter ------------------------------
__global__ void k_cvt(const float* __restrict__ src, __half* __restrict__ dh,
                      __half* __restrict__ dl) {
    int i = blockIdx.x * blockDim.x + threadIdx.x;
    float4 x = ((const float4*)src)[i];
    __half h0 = __float2half_rn(x.x), h1 = __float2half_rn(x.y);
    __half h2 = __float2half_rn(x.z), h3 = __float2half_rn(x.w);
    __half2 ph0 = {h0, h1}, ph1 = {h2, h3};
    __half2 pl0 = {__float2half_rn(x.x - __half2float(h0)),
                   __float2half_rn(x.y - __half2float(h1))};
    __half2 pl1 = {__float2half_rn(x.z - __half2float(h2)),
                   __float2half_rn(x.w - __half2float(h3))};
    ((__half2*)dh)[2 * i] = ph0;
    ((__half2*)dh)[2 * i + 1] = ph1;
    ((__half2*)dl)[2 * i] = pl0;
    ((__half2*)dl)[2 * i + 1] = pl1;
}

// ---------------- fp32 -> fp16 (single) converter ---------------------------
__global__ void k_cvt1(const float* __restrict__ src, __half* __restrict__ dh) {
    int i = blockIdx.x * blockDim.x + threadIdx.x;
    float4 x = ((const float4*)src)[i];
    __half2 p0 = {__float2half_rn(x.x), __float2half_rn(x.y)};
    __half2 p1 = {__float2half_rn(x.z), __float2half_rn(x.w)};
    ((__half2*)dh)[2 * i] = p0;
    ((__half2*)dh)[2 * i + 1] = p1;
}

// ======================= shared mma tile machinery ==========================
#define LG_KC 64
#define LG_COMP_BYTES (128 * 128)
#define LG_STAGE_BYTES (4 * LG_COMP_BYTES)
#define LG_SMEM_REQ (2 * LG_STAGE_BYTES + 1024)
// 1-product logits variant: 2 components per stage
#define L1_STAGE_BYTES (2 * LG_COMP_BYTES)
#define L1_SMEM_REQ (2 * L1_STAGE_BYTES + 1024)

template <int KCH, typename ISSUE>
__device__ __forceinline__ void mma_tile_128(uint32_t sb, ISSUE issue,
                                             float (&acc)[2][8][4],
                                             int warp, int lane) {
    int wm = warp & 3, wn = warp >> 2;
    issue(0, 0);
    for (int c = 0; c < KCH; c++) {
        if (c + 1 < KCH) {
            issue(c + 1, (c + 1) & 1);
            CP_WAIT(1);
        } else {
            CP_WAIT(0);
        }
        __syncthreads();
        uint32_t st = sb + (c & 1) * LG_STAGE_BYTES;
        uint32_t Ah_b = st, Al_b = st + LG_COMP_BYTES;
        uint32_t Bh_b = st + 2 * LG_COMP_BYTES, Bl_b = st + 3 * LG_COMP_BYTES;
        int lrow = lane & 15;
        uint32_t lcol = (uint32_t)((lane >> 4) << 4);
#pragma unroll
        for (int ks = 0; ks < 4; ks++) {
            uint32_t ah[2][4], al[2][4];
#pragma unroll
            for (int mt = 0; mt < 2; mt++) {
                int r = wm * 32 + mt * 16 + lrow;
                uint32_t bo = sw128((uint32_t)(r * 128 + ks * 32) + lcol);
                ldsm_x4(ah[mt], Ah_b + bo);
                ldsm_x4(al[mt], Al_b + bo);
            }
            uint32_t bh[4][4], bl[4][4];
#pragma unroll
            for (int p = 0; p < 4; p++) {
                int r = wn * 64 + p * 16 + lrow;
                uint32_t bo = sw128((uint32_t)(r * 128 + ks * 32) + lcol);
                ldsm_x4(bh[p], Bh_b + bo);
                ldsm_x4(bl[p], Bl_b + bo);
            }
#pragma unroll
            for (int mt = 0; mt < 2; mt++)
#pragma unroll
                for (int p = 0; p < 4; p++) {
#pragma unroll
                    for (int q = 0; q < 2; q++) {
                        int nt = p * 2 + q;
                        mma16816(acc[mt][nt], ah[mt], bh[p][q], bh[p][q + 2]);
                        mma16816(acc[mt][nt], ah[mt], bl[p][q], bl[p][q + 2]);
                        mma16816(acc[mt][nt], al[mt], bh[p][q], bh[p][q + 2]);
                    }
                }
        }
        __syncthreads();
    }
}

// ---------------- xW = emb[labels] @ W_ih^T + b_ih + b_hh (mma) ------------
__global__ __launch_bounds__(256) void k_xw_mma(const int* __restrict__ labels,
                                                const float* __restrict__ b_ih,
                                                const float* __restrict__ b_hh) {
    extern __shared__ char smraw[];
    __shared__ int rowlab[128];
    uint32_t sb = (smem_u32(smraw) + 1023u) & ~1023u;
    int tid = threadIdx.x, warp = tid >> 5, lane = tid & 31;
    int n0 = blockIdx.x * 128, m0 = blockIdx.y * 128;
    if (tid < 128) {
        int m = m0 + tid;
        int lab = labels[(m & 63) * T + (m >> 6)];
        rowlab[tid] = lab < 0 ? 0 : (lab >= V ? V - 1 : lab);
    }
    __syncthreads();
    auto issue = [&](int c, int stage) {
        uint32_t sbase = sb + stage * LG_STAGE_BYTES;
#pragma unroll
        for (int i = 0; i < 16; i++) {
            int slot = i * 256 + tid;
            int comp = slot >> 10, w = slot & 1023;
            int r = w >> 3, ch = w & 7;
            const __half* src;
            if (comp == 0)      src = g_embh + (size_t)rowlab[r] * D;
            else if (comp == 1) src = g_embl + (size_t)rowlab[r] * D;
            else if (comp == 2) src = g_wih_h + (size_t)(n0 + r) * D;
            else                src = g_wih_l + (size_t)(n0 + r) * D;
            src += c * LG_KC + ch * 8;
            uint32_t dst = sbase + comp * LG_COMP_BYTES + sw128(r * 128 + ch * 16);
            CP_ASYNC16(dst, src);
        }
        CP_COMMIT();
    };
    float acc[2][8][4] = {};
    mma_tile_128<D / LG_KC>(sb, issue, acc, warp, lane);
    int wm = warp & 3, wn = warp >> 2;
#pragma unroll
    for (int mt = 0; mt < 2; mt++) {
        int mrow = m0 + wm * 32 + mt * 16 + (lane >> 2);
#pragma unroll
        for (int nt = 0; nt < 8; nt++) {
            int n = n0 + wn * 64 + nt * 8 + (lane & 3) * 2;
            float2 bi = *(const float2*)(b_ih + n);
            float2 bh2 = *(const float2*)(b_hh + n);
            float2 o0 = {acc[mt][nt][0] + bi.x + bh2.x, acc[mt][nt][1] + bi.y + bh2.y};
            float2 o1 = {acc[mt][nt][2] + bi.x + bh2.x, acc[mt][nt][3] + bi.y + bh2.y};
            *(float2*)(g_xw + (size_t)mrow * GD + n) = o0;
            *(float2*)(g_xw + (size_t)(mrow + 8) * GD + n) = o1;
        }
    }
}

// ---------------- gates partial mma body (K=128 split, double-buffered) -----
// Needs 8*GT_COMP_BYTES (64KB) of smem at sm.
#define GT_COMP_BYTES (64 * 128)
#define GT_SMEM_REQ (8 * GT_COMP_BYTES)
__device__ __forceinline__ void gates_body(char* sm, int cta_n, int ksplit) {
    uint32_t sb = smem_u32(sm);
    int tid = threadIdx.x, warp = tid >> 5, lane = tid & 31;
    int n0 = cta_n * 64;
    int wm = warp & 1, wn = warp >> 1;
    int lrow = lane & 15;
    uint32_t lcol = (uint32_t)((lane >> 4) << 4);
    // issue both K-sub-chunks up front (double buffer)
#pragma unroll
    for (int sub = 0; sub < 2; sub++) {
        int kb = ksplit * 128 + sub * 64;
        uint32_t bb = sb + sub * (4 * GT_COMP_BYTES);
        const __half* srcs[4] = {g_hh16, g_hl16,
                                 g_whh_h + (size_t)n0 * D, g_whh_l + (size_t)n0 * D};
#pragma unroll
        for (int i = 0; i < 8; i++) {
            int slot = i * 256 + tid;
            int comp = slot >> 9, w = slot & 511;
            int r = w >> 3, ch = w & 7;
            const __half* src = srcs[comp] + (size_t)r * D + kb + ch * 8;
            uint32_t dst = bb + comp * GT_COMP_BYTES + sw128(r * 128 + ch * 16);
            CP_ASYNC16(dst, src);
        }
        CP_COMMIT();
    }
    float acc[2][2][4] = {};
#pragma unroll
    for (int sub = 0; sub < 2; sub++) {
        if (sub == 0) { CP_WAIT(1); } else { CP_WAIT(0); }
        __syncthreads();
        uint32_t bb = sb + sub * (4 * GT_COMP_BYTES);
        uint32_t Ah_b = bb, Al_b = bb + GT_COMP_BYTES;
        uint32_t Bh_b = bb + 2 * GT_COMP_BYTES, Bl_b = bb + 3 * GT_COMP_BYTES;
#pragma unroll
        for (int ks = 0; ks < 4; ks++) {
            uint32_t ah[2][4], al[2][4];
#pragma unroll
            for (int mt = 0; mt < 2; mt++) {
                int r = wm * 32 + mt * 16 + lrow;
                uint32_t bo = sw128((uint32_t)(r * 128 + ks * 32) + lcol);
                ldsm_x4(ah[mt], Ah_b + bo);
                ldsm_x4(al[mt], Al_b + bo);
            }
            uint32_t bh[4], bl[4];
            {
                int r = wn * 16 + lrow;
                uint32_t bo = sw128((uint32_t)(r * 128 + ks * 32) + lcol);
                ldsm_x4(bh, Bh_b + bo);
                ldsm_x4(bl, Bl_b + bo);
            }
#pragma unroll
            for (int mt = 0; mt < 2; mt++)
#pragma unroll
                for (int q = 0; q < 2; q++) {
                    mma16816(acc[mt][q], ah[mt], bh[q], bh[q + 2]);
                    mma16816(acc[mt][q], ah[mt], bl[q], bl[q + 2]);
                    mma16816(acc[mt][q], al[mt], bh[q], bh[q + 2]);
                }
        }
    }
    float* base = g_gpart + (size_t)ksplit * B * GD;
#pragma unroll
    for (int mt = 0; mt < 2; mt++) {
        int br = wm * 32 + mt * 16 + (lane >> 2);
#pragma unroll
        for (int q = 0; q < 2; q++) {
            int n = n0 + wn * 16 + q * 8 + (lane & 3) * 2;
            float2 o0 = {acc[mt][q][0], acc[mt][q][1]};
            float2 o1 = {acc[mt][q][2], acc[mt][q][3]};
            *(float2*)(base + (size_t)br * GD + n) = o0;
            *(float2*)(base + (size_t)(br + 8) * GD + n) = o1;
        }
    }
}

// standalone gates (for t=0): grid (32, 4), dynamic smem GT_SMEM_REQ
__global__ __launch_bounds__(256) void k_gates4() {
    extern __shared__ char smd[];
    gates_body(smd, blockIdx.x, blockIdx.y);
}

// ======= cell + scores (grid 128 pairs, 512 thr) ============================
__global__ __launch_bounds__(512) void k_cellsc(int t, const float* __restrict__ feats) {
    __shared__ __align__(16) float hs[D];
    int tid = threadIdx.x;
    int b = blockIdx.x >> 1, half = blockIdx.x & 1;

    // Phase 1: LSTM cell (redundant per pair)
    {
        int d = tid;
        const float* c_in = g_cbuf + (t & 1) * (B * D);
        float* c_out = g_cbuf + ((t + 1) & 1) * (B * D);
        const float* xwrow = g_xw + ((size_t)t * B + b) * GD;
        float ig = xwrow[d], fg = xwrow[D + d], gg = xwrow[2 * D + d], og = xwrow[3 * D + d];
#pragma unroll
        for (int ks = 0; ks < 4; ks++) {
            const float* gp = g_gpart + ((size_t)ks * B + b) * GD;
            ig += gp[d];
            fg += gp[D + d];
            gg += gp[2 * D + d];
            og += gp[3 * D + d];
        }
        float cn = sigf(fg) * c_in[b * D + d] + sigf(ig) * tanhf(gg);
        float hv = sigf(og) * tanhf(cn);
        hs[d] = hv;
        if (half == 0) {
            c_out[b * D + d] = cn;
            __half hh = __float2half_rn(hv);
            __half hl = __float2half_rn(hv - __half2float(hh));
            g_hh16[b * D + d] = hh;
            g_hl16[b * D + d] = hl;
            size_t mrow = (size_t)t * B + b;
            g_hcinh[mrow * 2 * D + d] = hh;
            g_hcinl[mrow * 2 * D + d] = hl;
        }
    }
    __syncthreads();

    // Phase 2: scores for s in [half*128, +128): 16 warps x 8 s -> global
    int warp = tid >> 5, lane = tid & 31;
    const float4* h4 = (const float4*)hs;
#pragma unroll
    for (int i = 0; i < 8; i++) {
        int s = half * 128 + warp * 8 + i;
        const float4* f4 = (const float4*)(feats + ((size_t)s * B + b) * D);
        float a = 0.f;
#pragma unroll
        for (int j = 0; j < 4; j++) {
            int ii = j * 32 + lane;
            float4 f = f4[ii], h = h4[ii];
            a = fmaf(f.x, h.x, fmaf(f.y, h.y, fmaf(f.z, h.z, fmaf(f.w, h.w, a))));
        }
#pragma unroll
        for (int o = 16; o; o >>= 1) a += __shfl_xor_sync(0xffffffffu, a, o);
        if (lane == 0) g_scraw[b * S + s] = a;
    }
}

// ======= heterogeneous: softmax+ctx(t) [CTAs 0-127] | gates(t+1) [128-255] ==
__global__ __launch_bounds__(256) void k_mix(int t) {
    extern __shared__ char smd[];
    int tid = threadIdx.x;
    if (blockIdx.x >= 128) {
        if (t + 1 >= T) return;
        int cta = blockIdx.x - 128;
        gates_body(smd, cta & 31, cta >> 5);
        return;
    }
    // ---- attention: softmax + ctx for (b, half) ----
    float* wall = (float*)smd;                 // 256 floats
    float* red = (float*)(smd + 1024);         // 256 floats
    float2* csum2 = (float2*)(smd + 2048);     // [2][128] float2
    int b = blockIdx.x >> 1, half = blockIdx.x & 1;

    float sv = g_scraw[b * S + tid];
    red[tid] = sv;
    __syncthreads();
    for (int st = 128; st; st >>= 1) {
        if (tid < st) red[tid] = fmaxf(red[tid], red[tid + st]);
        __syncthreads();
    }
    float mx = red[0];
    __syncthreads();
    float e = expf(sv - mx);
    red[tid] = e;
    __syncthreads();
    for (int st = 128; st; st >>= 1) {
        if (tid < st) red[tid] += red[tid + st];
        __syncthreads();
    }
    wall[tid] = e / red[0];
    __syncthreads();

    // ctx: d-half (256 dims = 128 half2), 2 s-shards of 128
    {
        int p = tid & 127, shard = tid >> 7;
        float2 a = {0.f, 0.f};
#pragma unroll 8
        for (int i = 0; i < 128; i++) {
            int s = shard * 128 + i;
            __half2 f = *((const __half2*)(g_feats16 + ((size_t)s * B + b) * D + half * 256) + p);
            float2 ff = __half22float2(f);
            float w = wall[s];
            a.x = fmaf(w, ff.x, a.x);
            a.y = fmaf(w, ff.y, a.y);
        }
        csum2[shard * 128 + p] = a;
        __syncthreads();
        if (tid < 128) {
            float2 c0 = csum2[tid], c1 = csum2[128 + tid];
            float cx = c0.x + c1.x, cy = c0.y + c1.y;
            __half hx = __float2half_rn(cx), hy = __float2half_rn(cy);
            __half2 ph = {hx, hy};
            __half2 pl = {__float2half_rn(cx - __half2float(hx)),
                          __float2half_rn(cy - __half2float(hy))};
            size_t mrow = (size_t)t * B + b;
            size_t off = mrow * 2 * D + D + half * 256 + 2 * tid;
            *(__half2*)&g_hcinh[off] = ph;
            *(__half2*)&g_hcinl[off] = pl;
        }
    }
}

// ---------------- hcall = [h, ctx] @ W_hc^T + b_hc (mma) --------------------
__global__ __launch_bounds__(256) void k_hc_mma(const float* __restrict__ b_hc) {
    extern __shared__ char smraw[];
    uint32_t sb = (smem_u32(smraw) + 1023u) & ~1023u;
    int tid = threadIdx.x, warp = tid >> 5, lane = tid & 31;
    int n0 = blockIdx.x * 128, m0 = blockIdx.y * 128;
    auto issue = [&](int c, int stage) {
        uint32_t sbase = sb + stage * LG_STAGE_BYTES;
#pragma unroll
        for (int i = 0; i < 16; i++) {
            int slot = i * 256 + tid;
            int comp = slot >> 10, w = slot & 1023;
            int r = w >> 3, ch = w & 7;
            const __half* src;
            if (comp == 0)      src = g_hcinh + (size_t)(m0 + r) * 2 * D;
            else if (comp == 1) src = g_hcinl + (size_t)(m0 + r) * 2 * D;
            else if (comp == 2) src = g_whc_h + (size_t)(n0 + r) * 2 * D;
            else                src = g_whc_l + (size_t)(n0 + r) * 2 * D;
            src += c * LG_KC + ch * 8;
            uint32_t dst = sbase + comp * LG_COMP_BYTES + sw128(r * 128 + ch * 16);
            CP_ASYNC16(dst, src);
        }
        CP_COMMIT();
    };
    float acc[2][8][4] = {};
    mma_tile_128<2 * D / LG_KC>(sb, issue, acc, warp, lane);
    int wm = warp & 3, wn = warp >> 2;
#pragma unroll
    for (int mt = 0; mt < 2; mt++) {
        int mrow = m0 + wm * 32 + mt * 16 + (lane >> 2);
#pragma unroll
        for (int nt = 0; nt < 8; nt++) {
            int n = n0 + wn * 64 + nt * 8 + (lane & 3) * 2;
            float2 bv = *(const float2*)(b_hc + n);
            float2 o0 = {acc[mt][nt][0] + bv.x, acc[mt][nt][1] + bv.y};
            float2 o1 = {acc[mt][nt][2] + bv.x, acc[mt][nt][3] + bv.y};
            *(float2*)(g_hcall + (size_t)mrow * D + n) = o0;
            *(float2*)(g_hcall + (size_t)(mrow + 8) * D + n) = o1;
        }
    }
}

// ---------------- LayerNorm + tanh -> pe (fp16 hi only) --------------------
__global__ __launch_bounds__(128) void k_ln_all(const float* __restrict__ ln_g,
                                                const float* __restrict__ ln_b) {
    int m = blockIdx.x;
    int tid = threadIdx.x;
    __shared__ float wsum[4];
    float4 x = *(const float4*)(g_hcall + (size_t)m * D + tid * 4);
    float s = x.x + x.y + x.z + x.w;
#pragma unroll
    for (int o = 16; o; o >>= 1) s += __shfl_xor_sync(0xffffffff, s, o);
    if ((tid & 31) == 0) wsum[tid >> 5] = s;
    __syncthreads();
    float mean = (wsum[0] + wsum[1] + wsum[2] + wsum[3]) * (1.f / D);
    float4 dv = {x.x - mean, x.y - mean, x.z - mean, x.w - mean};
    float v = dv.x * dv.x + dv.y * dv.y + dv.z * dv.z + dv.w * dv.w;
#pragma unroll
    for (int o = 16; o; o >>= 1) v += __shfl_xor_sync(0xffffffff, v, o);
    __syncthreads();
    if ((tid & 31) == 0) wsum[tid >> 5] = v;
    __syncthreads();
    float var = (wsum[0] + wsum[1] + wsum[2] + wsum[3]) * (1.f / D);
    float rs = rsqrtf(var + 1e-5f);
    float4 gl = *(const float4*)(ln_g + tid * 4);
    float4 bl = *(const float4*)(ln_b + tid * 4);
    float y0 = tanhf(fmaf(gl.x, dv.x * rs, bl.x));
    float y1 = tanhf(fmaf(gl.y, dv.y * rs, bl.y));
    float y2 = tanhf(fmaf(gl.z, dv.z * rs, bl.z));
    float y3 = tanhf(fmaf(gl.w, dv.w * rs, bl.w));
    __half2 p0 = {__float2half_rn(y0), __float2half_rn(y1)};
    __half2 p1 = {__float2half_rn(y2), __float2half_rn(y3)};
    size_t o = (size_t)m * D + tid * 4;
    *(__half2*)&g_peh[o] = p0;
    *(__half2*)&g_peh[o + 2] = p1;
}

// ============ logits via mma.sync, single product pe_h x emb_h ==============
__global__ __launch_bounds__(256) void k_logits_mma(const float* __restrict__ vbias,
                                                    float* __restrict__ out) {
    extern __shared__ char smraw[];
    uint32_t sb = (smem_u32(smraw) + 1023u) & ~1023u;
    int tid = threadIdx.x, warp = tid >> 5, lane = tid & 31;
    int m0 = blockIdx.x * 128, n0 = blockIdx.y * 128;
    const __half* srcs[2] = {g_peh + (size_t)m0 * D, g_embh + (size_t)n0 * D};
    auto issue = [&](int c, int stage) {
        uint32_t sbase = sb + stage * L1_STAGE_BYTES;
#pragma unroll
        for (int i = 0; i < 8; i++) {
            int slot = i * 256 + tid;            // 0..2047
            int comp = slot >> 10, w = slot & 1023;
            int r = w >> 3, ch = w & 7;
            const __half* src = srcs[comp] + (size_t)r * D + c * LG_KC + ch * 8;
            uint32_t dst = sbase + comp * LG_COMP_BYTES + sw128(r * 128 + ch * 16);
            CP_ASYNC16(dst, src);
        }
        CP_COMMIT();
    };
    float acc[2][8][4] = {};
    int wm = warp & 3, wn = warp >> 2;
    int lrow = lane & 15;
    uint32_t lcol = (uint32_t)((lane >> 4) << 4);
    issue(0, 0);
    for (int c = 0; c < D / LG_KC; c++) {
        if (c + 1 < D / LG_KC) {
            issue(c + 1, (c + 1) & 1);
            CP_WAIT(1);
        } else {
            CP_WAIT(0);
        }
        __syncthreads();
        uint32_t st = sb + (c & 1) * L1_STAGE_BYTES;
        uint32_t Ah_b = st, Bh_b = st + LG_COMP_BYTES;
#pragma unroll
        for (int ks = 0; ks < 4; ks++) {
            uint32_t ah[2][4];
#pragma unroll
            for (int mt = 0; mt < 2; mt++) {
                int r = wm * 32 + mt * 16 + lrow;
                uint32_t bo = sw128((uint32_t)(r * 128 + ks * 32) + lcol);
                ldsm_x4(ah[mt], Ah_b + bo);
            }
            uint32_t bh[4][4];
#pragma unroll
            for (int p = 0; p < 4; p++) {
                int r = wn * 64 + p * 16 + lrow;
                uint32_t bo = sw128((uint32_t)(r * 128 + ks * 32) + lcol);
                ldsm_x4(bh[p], Bh_b + bo);
            }
#pragma unroll
            for (int mt = 0; mt < 2; mt++)
#pragma unroll
                for (int p = 0; p < 4; p++) {
#pragma unroll
                    for (int q = 0; q < 2; q++) {
                        int nt = p * 2 + q;
                        mma16816(acc[mt][nt], ah[mt], bh[p][q], bh[p][q + 2]);
                    }
                }
        }
        __syncthreads();
    }
#pragma unroll
    for (int mt = 0; mt < 2; mt++) {
        int mrow = m0 + wm * 32 + mt * 16 + (lane >> 2);
#pragma unroll
        for (int nt = 0; nt < 8; nt++) {
            int n = n0 + wn * 64 + nt * 8 + (lane & 3) * 2;
            float2 bv = *(const float2*)(vbias + n);
            float2 o0 = {acc[mt][nt][0] + bv.x, acc[mt][nt][1] + bv.y};
            float2 o1 = {acc[mt][nt][2] + bv.x, acc[mt][nt][3] + bv.y};
            *(float2*)(out + (size_t)mrow * V + n) = o0;
            *(float2*)(out + (size_t)(mrow + 8) * V + n) = o1;
        }
    }
}

// ---------------- launch ----------------------------------------------------
extern "C" void kernel_launch(void* const* d_in, const int* in_sizes, int n_in,
                              void* d_out, int out_size) {
    const float* feats = (const float*)d_in[0];
    const int* labels = (const int*)d_in[1];
    const float* W_ih = (const float*)d_in[2];
    const float* W_hh = (const float*)d_in[3];
    const float* b_ih = (const float*)d_in[4];
    const float* b_hh = (const float*)d_in[5];
    const float* W_hc = (const float*)d_in[6];
    const float* b_hc = (const float*)d_in[7];
    const float* ln_g = (const float*)d_in[8];
    const float* ln_b = (const float*)d_in[9];
    const float* emb = (const float*)d_in[10];
    const float* vbias = (const float*)d_in[11];
    float* out = (float*)d_out;

    cudaFuncSetAttribute(k_logits_mma, cudaFuncAttributeMaxDynamicSharedMemorySize,
                         L1_SMEM_REQ);
    cudaFuncSetAttribute(k_xw_mma, cudaFuncAttributeMaxDynamicSharedMemorySize,
                         LG_SMEM_REQ);
    cudaFuncSetAttribute(k_hc_mma, cudaFuncAttributeMaxDynamicSharedMemorySize,
                         LG_SMEM_REQ);
    cudaFuncSetAttribute(k_mix, cudaFuncAttributeMaxDynamicSharedMemorySize,
                         GT_SMEM_REQ);
    cudaFuncSetAttribute(k_gates4, cudaFuncAttributeMaxDynamicSharedMemorySize,
                         GT_SMEM_REQ);

    __half *embh, *embl, *whhh, *whhl, *wihh, *wihl, *whch, *whcl, *f16;
    cudaGetSymbolAddress((void**)&embh, g_embh);
    cudaGetSymbolAddress((void**)&embl, g_embl);
    cudaGetSymbolAddress((void**)&whhh, g_whh_h);
    cudaGetSymbolAddress((void**)&whhl, g_whh_l);
    cudaGetSymbolAddress((void**)&wihh, g_wih_h);
    cudaGetSymbolAddress((void**)&wihl, g_wih_l);
    cudaGetSymbolAddress((void**)&whch, g_whc_h);
    cudaGetSymbolAddress((void**)&whcl, g_whc_l);
    cudaGetSymbolAddress((void**)&f16, g_feats16);

    k_init<<<(B * D) / 256, 256>>>(feats);
    k_cvt<<<(V * D / 4) / 256, 256>>>(emb, embh, embl);
    k_cvt<<<(GD * D / 4) / 256, 256>>>(W_hh, whhh, whhl);
    k_cvt<<<(GD * D / 4) / 256, 256>>>(W_ih, wihh, wihl);
    k_cvt<<<(D * 2 * D / 4) / 256, 256>>>(W_hc, whch, whcl);
    k_cvt1<<<((size_t)S * B * D / 4) / 256, 256>>>(feats, f16);
    k_xw_mma<<<dim3(GD / 128, (T * B) / 128), 256, LG_SMEM_REQ>>>(labels, b_ih, b_hh);
    k_gates4<<<dim3(32, 4), 256, GT_SMEM_REQ>>>();   // gates for t=0 from h0
    for (int t = 0; t < T; t++) {
        k_cellsc<<<2 * B, 512>>>(t, feats);
        k_mix<<<256, 256, GT_SMEM_REQ>>>(t);         // attn(t) || gates(t+1)
    }
    k_hc_mma<<<dim3(D / 128, (T * B) / 128), 256, LG_SMEM_REQ>>>(b_hc);
    k_ln_all<<<T * B, 128>>>(ln_g, ln_b);
    k_logits_mma<<<dim3((T * B) / 128, V / 128), 256, L1_SMEM_REQ>>>(vbias, out);
}

// round 16
// speedup vs baseline: 2.0708x; 1.1480x over previous
#include <cuda_runtime.h>
#include <cuda_fp16.h>
#include <math.h>
#include <cstdint>

#define S 256
#define B 64
#define D 512
#define T 64
#define V 32000
#define GD 2048  /* 4*D */

// ---------------- scratch (device globals; no runtime allocation) ----------
__device__ float g_xw[(size_t)T * B * GD];        // x@W_ih^T + b_ih + b_hh
__device__ float g_cbuf[2 * B * D];               // double-buffered cell state
__device__ float g_gpart[4 * B * GD];             // k-split partial gate sums
__device__ float g_hcall[(size_t)T * B * D];      // hc pre-LN
__device__ __half g_feats16[(size_t)S * B * D];   // feats in fp16 (ctx only)
__device__ __half g_peh[(size_t)T * B * D];
__device__ __half g_embh[(size_t)V * D];
__device__ __half g_embl[(size_t)V * D];
__device__ __half g_whh_h[(size_t)GD * D];
__device__ __half g_whh_l[(size_t)GD * D];
__device__ __half g_wih_h[(size_t)GD * D];
__device__ __half g_wih_l[(size_t)GD * D];
__device__ __half g_whc_h[(size_t)D * 2 * D];
__device__ __half g_whc_l[(size_t)D * 2 * D];
__device__ __half g_hh16[B * D];                  // current h, fp16 hi
__device__ __half g_hl16[B * D];                  // current h, fp16 lo
__device__ __half g_hcinh[(size_t)T * B * 2 * D]; // [h|ctx] hi, [4096,1024]
__device__ __half g_hcinl[(size_t)T * B * 2 * D]; // [h|ctx] lo
__device__ unsigned g_hsig;                       // h-ready counter (64 per step)

__device__ __forceinline__ float sigf(float x) { return 1.f / (1.f + expf(-x)); }

// ======================= PTX helpers ========================================
__device__ __forceinline__ uint32_t smem_u32(const void* p) {
    uint32_t a;
    asm("{ .reg .u64 t; cvta.to.shared.u64 t, %1; cvt.u32.u64 %0, t; }" : "=r"(a) : "l"(p));
    return a;
}
__device__ __forceinline__ uint32_t sw128(uint32_t off) { return off ^ ((off >> 3) & 0x70); }

#define CP_ASYNC16(dst, src) \
    asm volatile("cp.async.cg.shared.global [%0], [%1], 16;" :: "r"(dst), "l"(src) : "memory")
#define CP_COMMIT() asm volatile("cp.async.commit_group;" ::: "memory")
#define CP_WAIT(n) asm volatile("cp.async.wait_group %0;" :: "n"(n) : "memory")

__device__ __forceinline__ void ldsm_x4(uint32_t* r, uint32_t addr) {
    asm volatile("ldmatrix.sync.aligned.m8n8.x4.shared.b16 {%0,%1,%2,%3}, [%4];"
                 : "=r"(r[0]), "=r"(r[1]), "=r"(r[2]), "=r"(r[3]) : "r"(addr));
}
__device__ __forceinline__ void mma16816(float* c, const uint32_t* a, uint32_t b0, uint32_t b1) {
    asm volatile(
        "mma.sync.aligned.m16n8k16.row.col.f32.f16.f16.f32 "
        "{%0,%1,%2,%3}, {%4,%5,%6,%7}, {%8,%9}, {%0,%1,%2,%3};"
        : "+f"(c[0]), "+f"(c[1]), "+f"(c[2]), "+f"(c[3])
        : "r"(a[0]), "r"(a[1]), "r"(a[2]), "r"(a[3]), "r"(b0), "r"(b1));
}

// DSMEM: store fp32 into peer CTA's smem at same offset
__device__ __forceinline__ void dsmem_st_f32(uint32_t local_addr, int peer_rank, float v) {
    uint32_t remote;
    asm volatile("mapa.shared::cluster.u32 %0, %1, %2;"
                 : "=r"(remote) : "r"(local_addr), "r"(peer_rank));
    asm volatile("st.shared::cluster.f32 [%0], %1;" :: "r"(remote), "f"(v) : "memory");
}
#define CLUSTER_SYNC() do { \
    asm volatile("barrier.cluster.arrive.aligned;" ::: "memory"); \
    asm volatile("barrier.cluster.wait.aligned;" ::: "memory"); \
} while (0)

// ---------------- init h0 = c0 = feats[S-1] --------------------------------
__global__ void k_init(const float* __restrict__ feats) {
    int i = blockIdx.x * blockDim.x + threadIdx.x;
    if (i == 0) g_hsig = 0;
    float v = feats[(size_t)(S - 1) * B * D + i];
    g_cbuf[i] = v;                      // buffer 0
    __half hh = __float2half_rn(v);
    g_hh16[i] = hh;
    g_hl16[i] = __float2half_rn(v - __half2float(hh));
}

// ---------------- fp32 -> fp16 hi/lo converter ------------------------------
__global__ void k_cvt(const float* __restrict__ src, __half* __restrict__ dh,
                      __half* __restrict__ dl) {
    int i = blockIdx.x * blockDim.x + threadIdx.x;
    float4 x = ((const float4*)src)[i];
    __half h0 = __float2half_rn(x.x), h1 = __float2half_rn(x.y);
    __half h2 = __float2half_rn(x.z), h3 = __float2half_rn(x.w);
    __half2 ph0 = {h0, h1}, ph1 = {h2, h3};
    __half2 pl0 = {__float2half_rn(x.x - __half2float(h0)),
                   __float2half_rn(x.y - __half2float(h1))};
    __half2 pl1 = {__float2half_rn(x.z - __half2float(h2)),
                   __float2half_rn(x.w - __half2float(h3))};
    ((__half2*)dh)[2 * i] = ph0;
    ((__half2*)dh)[2 * i + 1] = ph1;
    ((__half2*)dl)[2 * i] = pl0;
    ((__half2*)dl)[2 * i + 1] = pl1;
}

// ---------------- fp32 -> fp16 (single) converter ---------------------------
__global__ void k_cvt1(const float* __restrict__ src, __half* __restrict__ dh) {
    int i = blockIdx.x * blockDim.x + threadIdx.x;
    float4 x = ((const float4*)src)[i];
    __half2 p0 = {__float2half_rn(x.x), __float2half_rn(x.y)};
    __half2 p1 = {__float2half_rn(x.z), __float2half_rn(x.w)};
    ((__half2*)dh)[2 * i] = p0;
    ((__half2*)dh)[2 * i + 1] = p1;
}

// ======================= shared mma tile machinery ==========================
#define LG_KC 64
#define LG_COMP_BYTES (128 * 128)
#define LG_STAGE_BYTES (4 * LG_COMP_BYTES)
#define LG_SMEM_REQ (2 * LG_STAGE_BYTES + 1024)
#define L1_STAGE_BYTES (2 * LG_COMP_BYTES)
#define L1_SMEM_REQ (2 * L1_STAGE_BYTES + 1024)

template <int KCH, typename ISSUE>
__device__ __forceinline__ void mma_tile_128(uint32_t sb, ISSUE issue,
                                             float (&acc)[2][8][4],
                                             int warp, int lane) {
    int wm = warp & 3, wn = warp >> 2;
    issue(0, 0);
    for (int c = 0; c < KCH; c++) {
        if (c + 1 < KCH) {
            issue(c + 1, (c + 1) & 1);
            CP_WAIT(1);
        } else {
            CP_WAIT(0);
        }
        __syncthreads();
        uint32_t st = sb + (c & 1) * LG_STAGE_BYTES;
        uint32_t Ah_b = st, Al_b = st + LG_COMP_BYTES;
        uint32_t Bh_b = st + 2 * LG_COMP_BYTES, Bl_b = st + 3 * LG_COMP_BYTES;
        int lrow = lane & 15;
        uint32_t lcol = (uint32_t)((lane >> 4) << 4);
#pragma unroll
        for (int ks = 0; ks < 4; ks++) {
            uint32_t ah[2][4], al[2][4];
#pragma unroll
            for (int mt = 0; mt < 2; mt++) {
                int r = wm * 32 + mt * 16 + lrow;
                uint32_t bo = sw128((uint32_t)(r * 128 + ks * 32) + lcol);
                ldsm_x4(ah[mt], Ah_b + bo);
                ldsm_x4(al[mt], Al_b + bo);
            }
            uint32_t bh[4][4], bl[4][4];
#pragma unroll
            for (int p = 0; p < 4; p++) {
                int r = wn * 64 + p * 16 + lrow;
                uint32_t bo = sw128((uint32_t)(r * 128 + ks * 32) + lcol);
                ldsm_x4(bh[p], Bh_b + bo);
                ldsm_x4(bl[p], Bl_b + bo);
            }
#pragma unroll
            for (int mt = 0; mt < 2; mt++)
#pragma unroll
                for (int p = 0; p < 4; p++) {
#pragma unroll
                    for (int q = 0; q < 2; q++) {
                        int nt = p * 2 + q;
                        mma16816(acc[mt][nt], ah[mt], bh[p][q], bh[p][q + 2]);
                        mma16816(acc[mt][nt], ah[mt], bl[p][q], bl[p][q + 2]);
                        mma16816(acc[mt][nt], al[mt], bh[p][q], bh[p][q + 2]);
                    }
                }
        }
        __syncthreads();
    }
}

// ---------------- xW = emb[labels] @ W_ih^T + b_ih + b_hh (mma) ------------
__global__ __launch_bounds__(256) void k_xw_mma(const int* __restrict__ labels,
                                                const float* __restrict__ b_ih,
                                                const float* __restrict__ b_hh) {
    extern __shared__ char smraw[];
    __shared__ int rowlab[128];
    uint32_t sb = (smem_u32(smraw) + 1023u) & ~1023u;
    int tid = threadIdx.x, warp = tid >> 5, lane = tid & 31;
    int n0 = blockIdx.x * 128, m0 = blockIdx.y * 128;
    if (tid < 128) {
        int m = m0 + tid;
        int lab = labels[(m & 63) * T + (m >> 6)];
        rowlab[tid] = lab < 0 ? 0 : (lab >= V ? V - 1 : lab);
    }
    __syncthreads();
    auto issue = [&](int c, int stage) {
        uint32_t sbase = sb + stage * LG_STAGE_BYTES;
#pragma unroll
        for (int i = 0; i < 16; i++) {
            int slot = i * 256 + tid;
            int comp = slot >> 10, w = slot & 1023;
            int r = w >> 3, ch = w & 7;
            const __half* src;
            if (comp == 0)      src = g_embh + (size_t)rowlab[r] * D;
            else if (comp == 1) src = g_embl + (size_t)rowlab[r] * D;
            else if (comp == 2) src = g_wih_h + (size_t)(n0 + r) * D;
            else                src = g_wih_l + (size_t)(n0 + r) * D;
            src += c * LG_KC + ch * 8;
            uint32_t dst = sbase + comp * LG_COMP_BYTES + sw128(r * 128 + ch * 16);
            CP_ASYNC16(dst, src);
        }
        CP_COMMIT();
    };
    float acc[2][8][4] = {};
    mma_tile_128<D / LG_KC>(sb, issue, acc, warp, lane);
    int wm = warp & 3, wn = warp >> 2;
#pragma unroll
    for (int mt = 0; mt < 2; mt++) {
        int mrow = m0 + wm * 32 + mt * 16 + (lane >> 2);
#pragma unroll
        for (int nt = 0; nt < 8; nt++) {
            int n = n0 + wn * 64 + nt * 8 + (lane & 3) * 2;
            float2 bi = *(const float2*)(b_ih + n);
            float2 bh2 = *(const float2*)(b_hh + n);
            float2 o0 = {acc[mt][nt][0] + bi.x + bh2.x, acc[mt][nt][1] + bi.y + bh2.y};
            float2 o1 = {acc[mt][nt][2] + bi.x + bh2.x, acc[mt][nt][3] + bi.y + bh2.y};
            *(float2*)(g_xw + (size_t)mrow * GD + n) = o0;
            *(float2*)(g_xw + (size_t)(mrow + 8) * GD + n) = o1;
        }
    }
}

// ---------------- gates partial mma body (512 thr, W-preload + h-wait) ------
#define GT_COMP_BYTES (64 * 128)
#define GT_SMEM_REQ (8 * GT_COMP_BYTES)
__device__ __forceinline__ void gates_body(char* sm, int cta_n, int ksplit,
                                           unsigned target) {
    uint32_t sb = smem_u32(sm);
    int tid = threadIdx.x, warp = tid >> 5, lane = tid & 31;
    int n0 = cta_n * 64;
    // preload W tiles (h-independent) for both K-sub-chunks
#pragma unroll
    for (int sub = 0; sub < 2; sub++) {
        int kb = ksplit * 128 + sub * 64;
        uint32_t bb = sb + sub * (4 * GT_COMP_BYTES);
#pragma unroll
        for (int i = 0; i < 2; i++) {
            int slot = i * 512 + tid;            // 0..1023
            int comp = 2 + (slot >> 9), w = slot & 511;
            int r = w >> 3, ch = w & 7;
            const __half* src = ((comp == 2) ? g_whh_h : g_whh_l) +
                                (size_t)(n0 + r) * D + kb + ch * 8;
            uint32_t dst = bb + comp * GT_COMP_BYTES + sw128(r * 128 + ch * 16);
            CP_ASYNC16(dst, src);
        }
        CP_COMMIT();
    }
    // wait for h(t) (spin hidden behind the W prefetch above)
    if (target) {
        if (tid == 0) {
            while (*(volatile unsigned*)&g_hsig < target) {}
            __threadfence();
        }
        __syncthreads();
    }
    // load h tiles for both sub-chunks
#pragma unroll
    for (int sub = 0; sub < 2; sub++) {
        int kb = ksplit * 128 + sub * 64;
        uint32_t bb = sb + sub * (4 * GT_COMP_BYTES);
#pragma unroll
        for (int i = 0; i < 2; i++) {
            int slot = i * 512 + tid;
            int comp = slot >> 9, w = slot & 511;
            int r = w >> 3, ch = w & 7;
            const __half* src = ((comp == 0) ? g_hh16 : g_hl16) +
                                (size_t)r * D + kb + ch * 8;
            uint32_t dst = bb + comp * GT_COMP_BYTES + sw128(r * 128 + ch * 16);
            CP_ASYNC16(dst, src);
        }
        CP_COMMIT();
    }
    // compute: warps 0-7 (wm = warp&1, wn = (warp>>1))
    int wm = warp & 1, wn = (warp >> 1) & 3;
    bool compute = (warp < 8);
    int lrow = lane & 15;
    uint32_t lcol = (uint32_t)((lane >> 4) << 4);
    float acc[2][2][4] = {};
#pragma unroll
    for (int sub = 0; sub < 2; sub++) {
        if (sub == 0) { CP_WAIT(1); } else { CP_WAIT(0); }
        __syncthreads();
        if (compute) {
            uint32_t bb = sb + sub * (4 * GT_COMP_BYTES);
            uint32_t Ah_b = bb, Al_b = bb + GT_COMP_BYTES;
            uint32_t Bh_b = bb + 2 * GT_COMP_BYTES, Bl_b = bb + 3 * GT_COMP_BYTES;
#pragma unroll
            for (int ks = 0; ks < 4; ks++) {
                uint32_t ah[2][4], al[2][4];
#pragma unroll
                for (int mt = 0; mt < 2; mt++) {
                    int r = wm * 32 + mt * 16 + lrow;
                    uint32_t bo = sw128((uint32_t)(r * 128 + ks * 32) + lcol);
                    ldsm_x4(ah[mt], Ah_b + bo);
                    ldsm_x4(al[mt], Al_b + bo);
                }
                uint32_t bh[4], bl[4];
                {
                    int r = wn * 16 + lrow;
                    uint32_t bo = sw128((uint32_t)(r * 128 + ks * 32) + lcol);
                    ldsm_x4(bh, Bh_b + bo);
                    ldsm_x4(bl, Bl_b + bo);
                }
#pragma unroll
                for (int mt = 0; mt < 2; mt++)
#pragma unroll
                    for (int q = 0; q < 2; q++) {
                        mma16816(acc[mt][q], ah[mt], bh[q], bh[q + 2]);
                        mma16816(acc[mt][q], ah[mt], bl[q], bl[q + 2]);
                        mma16816(acc[mt][q], al[mt], bh[q], bh[q + 2]);
                    }
            }
        }
    }
    if (compute) {
        float* base = g_gpart + (size_t)ksplit * B * GD;
#pragma unroll
        for (int mt = 0; mt < 2; mt++) {
            int br = wm * 32 + mt * 16 + (lane >> 2);
#pragma unroll
            for (int q = 0; q < 2; q++) {
                int n = n0 + wn * 16 + q * 8 + (lane & 3) * 2;
                float2 o0 = {acc[mt][q][0], acc[mt][q][1]};
                float2 o1 = {acc[mt][q][2], acc[mt][q][3]};
                *(float2*)(base + (size_t)br * GD + n) = o0;
                *(float2*)(base + (size_t)(br + 8) * GD + n) = o1;
            }
        }
    }
}

// standalone gates for t=0 (h0 ready, target=0): grid (32, 4), 512 thr
__global__ __launch_bounds__(512, 2) void k_gates4() {
    extern __shared__ char smd[];
    gates_body(smd, blockIdx.x, blockIdx.y, 0u);
}

// ===== fused step: [attn cluster pairs: CTAs 0-127] | [gates(t+1): 128-255] =
// attn: cell(t) (redundant per pair) -> signal h -> scores s-half -> DSMEM
//       exchange -> softmax -> ctx d-half (fp16 feats)
// gates: preload W_hh, spin on h signal, mma gates(t+1)
__global__ __launch_bounds__(512, 2) __cluster_dims__(2, 1, 1)
void k_step(int t, const float* __restrict__ feats) {
    extern __shared__ char smd[];
    int tid = threadIdx.x;
    if (blockIdx.x >= 128) {
        if (t + 1 >= T) return;
        int cta = blockIdx.x - 128;
        gates_body(smd, cta & 31, cta >> 5, 64u * (unsigned)(t + 1));
        return;
    }
    float* hs = (float*)smd;                   // 512 f
    float* wall = (float*)(smd + 2048);        // 256 f
    float* red = (float*)(smd + 3072);         // 256 f
    float2* csum2 = (float2*)(smd + 4096);     // [4][128] f2
    int b = blockIdx.x >> 1, half = blockIdx.x & 1, peer = half ^ 1;

    // Phase 1: LSTM cell (redundant per pair)
    {
        int d = tid;
        const float* c_in = g_cbuf + (t & 1) * (B * D);
        float* c_out = g_cbuf + ((t + 1) & 1) * (B * D);
        const float* xwrow = g_xw + ((size_t)t * B + b) * GD;
        float ig = xwrow[d], fg = xwrow[D + d], gg = xwrow[2 * D + d], og = xwrow[3 * D + d];
#pragma unroll
        for (int ks = 0; ks < 4; ks++) {
            const float* gp = g_gpart + ((size_t)ks * B + b) * GD;
            ig += gp[d];
            fg += gp[D + d];
            gg += gp[2 * D + d];
            og += gp[3 * D + d];
        }
        float cn = sigf(fg) * c_in[b * D + d] + sigf(ig) * tanhf(gg);
        float hv = sigf(og) * tanhf(cn);
        hs[d] = hv;
        if (half == 0) {
            c_out[b * D + d] = cn;
            __half hh = __float2half_rn(hv);
            __half hl = __float2half_rn(hv - __half2float(hh));
            g_hh16[b * D + d] = hh;
            g_hl16[b * D + d] = hl;
            size_t mrow = (size_t)t * B + b;
            g_hcinh[mrow * 2 * D + d] = hh;
            g_hcinl[mrow * 2 * D + d] = hl;
        }
    }
    __syncthreads();
    if (half == 0 && tid == 0) {
        __threadfence();
        atomicAdd(&g_hsig, 1u);
    }

    // Phase 2: scores for s in [half*128, +128): 16 warps x 8 s
    int warp = tid >> 5, lane = tid & 31;
    const float4* h4 = (const float4*)hs;
#pragma unroll
    for (int i = 0; i < 8; i++) {
        int s = half * 128 + warp * 8 + i;
        const float4* f4 = (const float4*)(feats + ((size_t)s * B + b) * D);
        float a = 0.f;
#pragma unroll
        for (int j = 0; j < 4; j++) {
            int ii = j * 32 + lane;
            float4 f = f4[ii], h = h4[ii];
            a = fmaf(f.x, h.x, fmaf(f.y, h.y, fmaf(f.z, h.z, fmaf(f.w, h.w, a))));
        }
#pragma unroll
        for (int o = 16; o; o >>= 1) a += __shfl_xor_sync(0xffffffffu, a, o);
        if (lane == 0) {
            wall[s] = a;
            dsmem_st_f32(smem_u32(&wall[s]), peer, a);
        }
    }
    CLUSTER_SYNC();   // peer scores visible

    // Phase 3: softmax over wall[0..255]
    float sv = (tid < S) ? wall[tid] : -1e30f;
    if (tid < 256) red[tid] = sv;
    __syncthreads();
    for (int st = 128; st; st >>= 1) {
        if (tid < st) red[tid] = fmaxf(red[tid], red[tid + st]);
        __syncthreads();
    }
    float mx = red[0];
    __syncthreads();
    float e = 0.f;
    if (tid < S) {
        e = expf(sv - mx);
        red[tid] = e;
    }
    __syncthreads();
    for (int st = 128; st; st >>= 1) {
        if (tid < st) red[tid] += red[tid + st];
        __syncthreads();
    }
    if (tid < S) wall[tid] = e / red[0];
    __syncthreads();

    // Phase 4: ctx for d in [half*256, +256): 4 s-shards of 64, fp16 feats
    {
        int p = tid & 127, shard = tid >> 7;
        float2 a = {0.f, 0.f};
#pragma unroll 8
        for (int i = 0; i < 64; i++) {
            int s = shard * 64 + i;
            __half2 f = *((const __half2*)(g_feats16 + ((size_t)s * B + b) * D + half * 256) + p);
            float2 ff = __half22float2(f);
            float w = wall[s];
            a.x = fmaf(w, ff.x, a.x);
            a.y = fmaf(w, ff.y, a.y);
        }
        csum2[shard * 128 + p] = a;
        __syncthreads();
        if (tid < 128) {
            float2 c0 = csum2[tid], c1 = csum2[128 + tid];
            float2 c2 = csum2[256 + tid], c3 = csum2[384 + tid];
            float cx = c0.x + c1.x + c2.x + c3.x;
            float cy = c0.y + c1.y + c2.y + c3.y;
            __half hx = __float2half_rn(cx), hy = __float2half_rn(cy);
            __half2 ph = {hx, hy};
            __half2 pl = {__float2half_rn(cx - __half2float(hx)),
                          __float2half_rn(cy - __half2float(hy))};
            size_t mrow = (size_t)t * B + b;
            size_t off = mrow * 2 * D + D + half * 256 + 2 * tid;
            *(__half2*)&g_hcinh[off] = ph;
            *(__half2*)&g_hcinl[off] = pl;
        }
    }
}

// ---------------- hcall = [h, ctx] @ W_hc^T + b_hc (mma) --------------------
__global__ __launch_bounds__(256) void k_hc_mma(const float* __restrict__ b_hc) {
    extern __shared__ char smraw[];
    uint32_t sb = (smem_u32(smraw) + 1023u) & ~1023u;
    int tid = threadIdx.x, warp = tid >> 5, lane = tid & 31;
    int n0 = blockIdx.x * 128, m0 = blockIdx.y * 128;
    auto issue = [&](int c, int stage) {
        uint32_t sbase = sb + stage * LG_STAGE_BYTES;
#pragma unroll
        for (int i = 0; i < 16; i++) {
            int slot = i * 256 + tid;
            int comp = slot >> 10, w = slot & 1023;
            int r = w >> 3, ch = w & 7;
            const __half* src;
            if (comp == 0)      src = g_hcinh + (size_t)(m0 + r) * 2 * D;
            else if (comp == 1) src = g_hcinl + (size_t)(m0 + r) * 2 * D;
            else if (comp == 2) src = g_whc_h + (size_t)(n0 + r) * 2 * D;
            else                src = g_whc_l + (size_t)(n0 + r) * 2 * D;
            src += c * LG_KC + ch * 8;
            uint32_t dst = sbase + comp * LG_COMP_BYTES + sw128(r * 128 + ch * 16);
            CP_ASYNC16(dst, src);
        }
        CP_COMMIT();
    };
    float acc[2][8][4] = {};
    mma_tile_128<2 * D / LG_KC>(sb, issue, acc, warp, lane);
    int wm = warp & 3, wn = warp >> 2;
#pragma unroll
    for (int mt = 0; mt < 2; mt++) {
        int mrow = m0 + wm * 32 + mt * 16 + (lane >> 2);
#pragma unroll
        for (int nt = 0; nt < 8; nt++) {
            int n = n0 + wn * 64 + nt * 8 + (lane & 3) * 2;
            float2 bv = *(const float2*)(b_hc + n);
            float2 o0 = {acc[mt][nt][0] + bv.x, acc[mt][nt][1] + bv.y};
            float2 o1 = {acc[mt][nt][2] + bv.x, acc[mt][nt][3] + bv.y};
            *(float2*)(g_hcall + (size_t)mrow * D + n) = o0;
            *(float2*)(g_hcall + (size_t)(mrow + 8) * D + n) = o1;
        }
    }
}

// ---------------- LayerNorm + tanh -> pe (fp16 hi only) --------------------
__global__ __launch_bounds__(128) void k_ln_all(const float* __restrict__ ln_g,
                                                const float* __restrict__ ln_b) {
    int m = blockIdx.x;
    int tid = threadIdx.x;
    __shared__ float wsum[4];
    float4 x = *(const float4*)(g_hcall + (size_t)m * D + tid * 4);
    float s = x.x + x.y + x.z + x.w;
#pragma unroll
    for (int o = 16; o; o >>= 1) s += __shfl_xor_sync(0xffffffff, s, o);
    if ((tid & 31) == 0) wsum[tid >> 5] = s;
    __syncthreads();
    float mean = (wsum[0] + wsum[1] + wsum[2] + wsum[3]) * (1.f / D);
    float4 dv = {x.x - mean, x.y - mean, x.z - mean, x.w - mean};
    float v = dv.x * dv.x + dv.y * dv.y + dv.z * dv.z + dv.w * dv.w;
#pragma unroll
    for (int o = 16; o; o >>= 1) v += __shfl_xor_sync(0xffffffff, v, o);
    __syncthreads();
    if ((tid & 31) == 0) wsum[tid >> 5] = v;
    __syncthreads();
    float var = (wsum[0] + wsum[1] + wsum[2] + wsum[3]) * (1.f / D);
    float rs = rsqrtf(var + 1e-5f);
    float4 gl = *(const float4*)(ln_g + tid * 4);
    float4 bl = *(const float4*)(ln_b + tid * 4);
    float y0 = tanhf(fmaf(gl.x, dv.x * rs, bl.x));
    float y1 = tanhf(fmaf(gl.y, dv.y * rs, bl.y));
    float y2 = tanhf(fmaf(gl.z, dv.z * rs, bl.z));
    float y3 = tanhf(fmaf(gl.w, dv.w * rs, bl.w));
    __half2 p0 = {__float2half_rn(y0), __float2half_rn(y1)};
    __half2 p1 = {__float2half_rn(y2), __float2half_rn(y3)};
    size_t o = (size_t)m * D + tid * 4;
    *(__half2*)&g_peh[o] = p0;
    *(__half2*)&g_peh[o + 2] = p1;
}

// ============ logits via mma.sync, single product pe_h x emb_h ==============
__global__ __launch_bounds__(256) void k_logits_mma(const float* __restrict__ vbias,
                                                    float* __restrict__ out) {
    extern __shared__ char smraw[];
    uint32_t sb = (smem_u32(smraw) + 1023u) & ~1023u;
    int tid = threadIdx.x, warp = tid >> 5, lane = tid & 31;
    int m0 = blockIdx.x * 128, n0 = blockIdx.y * 128;
    const __half* srcs[2] = {g_peh + (size_t)m0 * D, g_embh + (size_t)n0 * D};
    auto issue = [&](int c, int stage) {
        uint32_t sbase = sb + stage * L1_STAGE_BYTES;
#pragma unroll
        for (int i = 0; i < 8; i++) {
            int slot = i * 256 + tid;
            int comp = slot >> 10, w = slot & 1023;
            int r = w >> 3, ch = w & 7;
            const __half* src = srcs[comp] + (size_t)r * D + c * LG_KC + ch * 8;
            uint32_t dst = sbase + comp * LG_COMP_BYTES + sw128(r * 128 + ch * 16);
            CP_ASYNC16(dst, src);
        }
        CP_COMMIT();
    };
    float acc[2][8][4] = {};
    int wm = warp & 3, wn = warp >> 2;
    int lrow = lane & 15;
    uint32_t lcol = (uint32_t)((lane >> 4) << 4);
    issue(0, 0);
    for (int c = 0; c < D / LG_KC; c++) {
        if (c + 1 < D / LG_KC) {
            issue(c + 1, (c + 1) & 1);
            CP_WAIT(1);
        } else {
            CP_WAIT(0);
        }
        __syncthreads();
        uint32_t st = sb + (c & 1) * L1_STAGE_BYTES;
        uint32_t Ah_b = st, Bh_b = st + LG_COMP_BYTES;
#pragma unroll
        for (int ks = 0; ks < 4; ks++) {
            uint32_t ah[2][4];
#pragma unroll
            for (int mt = 0; mt < 2; mt++) {
                int r = wm * 32 + mt * 16 + lrow;
                uint32_t bo = sw128((uint32_t)(r * 128 + ks * 32) + lcol);
                ldsm_x4(ah[mt], Ah_b + bo);
            }
            uint32_t bh[4][4];
#pragma unroll
            for (int p = 0; p < 4; p++) {
                int r = wn * 64 + p * 16 + lrow;
                uint32_t bo = sw128((uint32_t)(r * 128 + ks * 32) + lcol);
                ldsm_x4(bh[p], Bh_b + bo);
            }
#pragma unroll
            for (int mt = 0; mt < 2; mt++)
#pragma unroll
                for (int p = 0; p < 4; p++) {
#pragma unroll
                    for (int q = 0; q < 2; q++) {
                        int nt = p * 2 + q;
                        mma16816(acc[mt][nt], ah[mt], bh[p][q], bh[p][q + 2]);
                    }
                }
        }
        __syncthreads();
    }
#pragma unroll
    for (int mt = 0; mt < 2; mt++) {
        int mrow = m0 + wm * 32 + mt * 16 + (lane >> 2);
#pragma unroll
        for (int nt = 0; nt < 8; nt++) {
            int n = n0 + wn * 64 + nt * 8 + (lane & 3) * 2;
            float2 bv = *(const float2*)(vbias + n);
            float2 o0 = {acc[mt][nt][0] + bv.x, acc[mt][nt][1] + bv.y};
            float2 o1 = {acc[mt][nt][2] + bv.x, acc[mt][nt][3] + bv.y};
            *(float2*)(out + (size_t)mrow * V + n) = o0;
            *(float2*)(out + (size_t)(mrow + 8) * V + n) = o1;
        }
    }
}

// ---------------- launch ----------------------------------------------------
extern "C" void kernel_launch(void* const* d_in, const int* in_sizes, int n_in,
                              void* d_out, int out_size) {
    const float* feats = (const float*)d_in[0];
    const int* labels = (const int*)d_in[1];
    const float* W_ih = (const float*)d_in[2];
    const float* W_hh = (const float*)d_in[3];
    const float* b_ih = (const float*)d_in[4];
    const float* b_hh = (const float*)d_in[5];
    const float* W_hc = (const float*)d_in[6];
    const float* b_hc = (const float*)d_in[7];
    const float* ln_g = (const float*)d_in[8];
    const float* ln_b = (const float*)d_in[9];
    const float* emb = (const float*)d_in[10];
    const float* vbias = (const float*)d_in[11];
    float* out = (float*)d_out;

    cudaFuncSetAttribute(k_logits_mma, cudaFuncAttributeMaxDynamicSharedMemorySize,
                         L1_SMEM_REQ);
    cudaFuncSetAttribute(k_xw_mma, cudaFuncAttributeMaxDynamicSharedMemorySize,
                         LG_SMEM_REQ);
    cudaFuncSetAttribute(k_hc_mma, cudaFuncAttributeMaxDynamicSharedMemorySize,
                         LG_SMEM_REQ);
    cudaFuncSetAttribute(k_step, cudaFuncAttributeMaxDynamicSharedMemorySize,
                         GT_SMEM_REQ);
    cudaFuncSetAttribute(k_gates4, cudaFuncAttributeMaxDynamicSharedMemorySize,
                         GT_SMEM_REQ);

    __half *embh, *embl, *whhh, *whhl, *wihh, *wihl, *whch, *whcl, *f16;
    cudaGetSymbolAddress((void**)&embh, g_embh);
    cudaGetSymbolAddress((void**)&embl, g_embl);
    cudaGetSymbolAddress((void**)&whhh, g_whh_h);
    cudaGetSymbolAddress((void**)&whhl, g_whh_l);
    cudaGetSymbolAddress((void**)&wihh, g_wih_h);
    cudaGetSymbolAddress((void**)&wihl, g_wih_l);
    cudaGetSymbolAddress((void**)&whch, g_whc_h);
    cudaGetSymbolAddress((void**)&whcl, g_whc_l);
    cudaGetSymbolAddress((void**)&f16, g_feats16);

    k_init<<<(B * D) / 256, 256>>>(feats);
    k_cvt<<<(V * D / 4) / 256, 256>>>(emb, embh, embl);
    k_cvt<<<(GD * D / 4) / 256, 256>>>(W_hh, whhh, whhl);
    k_cvt<<<(GD * D / 4) / 256, 256>>>(W_ih, wihh, wihl);
    k_cvt<<<(D * 2 * D / 4) / 256, 256>>>(W_hc, whch, whcl);
    k_cvt1<<<((size_t)S * B * D / 4) / 256, 256>>>(feats, f16);
    k_xw_mma<<<dim3(GD / 128, (T * B) / 128), 256, LG_SMEM_REQ>>>(labels, b_ih, b_hh);
    k_gates4<<<dim3(32, 4), 512, GT_SMEM_REQ>>>();   // gates for t=0 from h0
    for (int t = 0; t < T; t++) {
        k_step<<<256, 512, GT_SMEM_REQ>>>(t, feats); // attn(t) || gates(t+1)
    }
    k_hc_mma<<<dim3(D / 128, (T * B) / 128), 256, LG_SMEM_REQ>>>(b_hc);
    k_ln_all<<<T * B, 128>>>(ln_g, ln_b);
    k_logits_mma<<<dim3((T * B) / 128, V / 128), 256, L1_SMEM_REQ>>>(vbias, out);
}